// round 1
// baseline (speedup 1.0000x reference)
#include <cuda_runtime.h>
#include <math.h>

#define L_LEN 15872
#define NTILE 248          // L / 64

// ---------------- device scratch (static allocation is allowed) ----------------
__device__ float g_cond[4 * 80 * L_LEN];
__device__ float g_res0[4 * 120 * L_LEN];
__device__ float g_res1[4 * 120 * L_LEN];
__device__ float g_skip[4 * 240 * L_LEN];
__device__ float g_h[4 * 256 * L_LEN];

__device__ float g_wg [16 * 320 * 240];   // [blk][kin][cout]  kin: 0-119 res(t-d), 120-239 res(t), 240-319 cond
__device__ float g_wsr[16 * 120 * 360];   // [blk][r][orow]    orow: 0-239 skip, 240-359 res
__device__ float g_wh1[240 * 256];        // [k][co]
__device__ float g_wh2[256 * 256];        // [k][co]
__device__ float g_bg [16 * 240];         // b_gate + b_cond

// ---------------- weight preparation (transpose into GEMM layouts) ----------------
__global__ void prep_kernel(const float* __restrict__ w_gate, const float* __restrict__ b_gate,
                            const float* __restrict__ w_cond, const float* __restrict__ b_cond,
                            const float* __restrict__ w_res,  const float* __restrict__ w_skip,
                            const float* __restrict__ w_h1,   const float* __restrict__ w_h2)
{
    const int n1 = 16 * 320 * 240;
    const int n2 = 16 * 120 * 360;
    const int n3 = 240 * 256;
    const int n4 = 256 * 256;
    const int n5 = 16 * 240;
    const int total = n1 + n2 + n3 + n4 + n5;
    for (int idx = blockIdx.x * blockDim.x + threadIdx.x; idx < total;
         idx += gridDim.x * blockDim.x) {
        int i2 = idx;
        if (i2 < n1) {
            int blk = i2 / (320 * 240);
            int rem = i2 % (320 * 240);
            int kin = rem / 240, c = rem % 240;
            float v;
            if (kin < 120)       v = w_gate[(((blk * 240) + c) * 120 + kin) * 2 + 0];
            else if (kin < 240)  v = w_gate[(((blk * 240) + c) * 120 + (kin - 120)) * 2 + 1];
            else                 v = w_cond[((blk * 240) + c) * 80 + (kin - 240)];
            g_wg[i2] = v;
        } else if ((i2 -= n1) < n2) {
            int blk = i2 / (120 * 360);
            int rem = i2 % (120 * 360);
            int r = rem / 360, orow = rem % 360;
            float v = (orow < 240) ? w_skip[((blk * 240) + orow) * 120 + r]
                                   : w_res [((blk * 120) + (orow - 240)) * 120 + r];
            g_wsr[i2] = v;
        } else if ((i2 -= n2) < n3) {
            int k = i2 / 256, co = i2 % 256;
            g_wh1[i2] = w_h1[co * 240 + k];
        } else if ((i2 -= n3) < n4) {
            int k = i2 / 256, co = i2 % 256;
            g_wh2[i2] = w_h2[co * 256 + k];
        } else {
            i2 -= n4;
            g_bg[i2] = b_gate[i2] + b_cond[i2];
        }
    }
}

// ---------------- residual init: res0[b,r,t] = w_in[r]*wav[b,t]+b_in[r] ----------------
__global__ void init_kernel(const float* __restrict__ wav, const float* __restrict__ w_in,
                            const float* __restrict__ b_in)
{
    const int total = 4 * 120 * L_LEN;
    for (int idx = blockIdx.x * blockDim.x + threadIdx.x; idx < total;
         idx += gridDim.x * blockDim.x) {
        int t = idx % L_LEN;
        int br = idx / L_LEN;
        int r = br % 120, b = br / 120;
        g_res0[idx] = w_in[r] * wav[b * L_LEN + t] + b_in[r];
    }
}

// ---------------- transposed-conv upsample, phase-structured ----------------
// cond[b,o,256u+p] = b_up[o] + sum_{v,m} mel[b,m,u-v] * w_up[m,o,400+p+256v],  v in {-2..1}
__global__ void __launch_bounds__(256) upsample_kernel(const float* __restrict__ mel,
                                                       const float* __restrict__ w_up,
                                                       const float* __restrict__ b_up)
{
    extern __shared__ float sm[];
    float* mel_s = sm;                 // [4][80][68], index j+1, zero-padded
    float* ws    = sm + 4 * 80 * 68;   // [4 v][80 m][80 o]

    const int p = blockIdx.x;
    const int tid = threadIdx.x;

    for (int idx = tid; idx < 4 * 80 * 68; idx += 256) mel_s[idx] = 0.f;
    __syncthreads();
    for (int idx = tid; idx < 4 * 80 * 63; idx += 256) {
        int j = idx % 63;
        int bm = idx / 63;
        mel_s[bm * 68 + j + 1] = mel[idx];
    }
    bool valid[4];
#pragma unroll
    for (int v = 0; v < 4; v++) {
        int kk = 400 + p + 256 * (v - 2);
        valid[v] = (kk >= 0) && (kk < 800);
        if (valid[v]) {
            for (int idx = tid; idx < 6400; idx += 256) {
                int m = idx / 80, o = idx % 80;
                ws[(v * 80 + m) * 80 + o] = w_up[(m * 80 + o) * 800 + kk];
            }
        }
    }
    __syncthreads();

    for (int tile = tid; tile < 320; tile += 256) {
        int og = tile >> 5;           // 0..9
        int b  = (tile >> 3) & 3;
        int ug = tile & 7;
        int o0 = og * 8, u0 = ug * 8;
        float acc[8][8];
#pragma unroll
        for (int a = 0; a < 8; a++)
#pragma unroll
            for (int c = 0; c < 8; c++) acc[a][c] = 0.f;

        const float* msb = mel_s + b * 80 * 68;
#pragma unroll
        for (int v = 0; v < 4; v++) {
            if (!valid[v]) continue;
            int vv = v - 2;
#pragma unroll 4
            for (int m = 0; m < 80; m++) {
                const float* wr = ws + (v * 80 + m) * 80 + o0;
                float4 wA = *(const float4*)wr;
                float4 wB = *(const float4*)(wr + 4);
                float wv[8] = {wA.x, wA.y, wA.z, wA.w, wB.x, wB.y, wB.z, wB.w};
                const float* xr = msb + m * 68 + (u0 - vv) + 1;
                float xv[8];
#pragma unroll
                for (int c = 0; c < 8; c++) xv[c] = xr[c];
#pragma unroll
                for (int a = 0; a < 8; a++)
#pragma unroll
                    for (int c = 0; c < 8; c++)
                        acc[a][c] = fmaf(wv[a], xv[c], acc[a][c]);
            }
        }
#pragma unroll
        for (int a = 0; a < 8; a++) {
            float bo = b_up[o0 + a];
#pragma unroll
            for (int c = 0; c < 8; c++) {
                int u = u0 + c;
                if (u < 62)
                    g_cond[((size_t)b * 80 + o0 + a) * L_LEN + 256 * u + p] = acc[a][c] + bo;
            }
        }
    }
}

// ---------------- fused residual block: gated GEMM + activation + skip/res GEMM ----------------
__global__ void __launch_bounds__(256, 2) block_kernel(const float* __restrict__ b_skip_all,
                                                       const float* __restrict__ b_res_all,
                                                       int blk, int d, int first, int parity)
{
    extern __shared__ float sm[];
    float* Xs = sm;                    // 320*64 inputs; rows 0-119 become z after phase A
    float* Ws = sm + 320 * 64;         // weight chunk, up to 12*360

    const float* res_in  = parity ? g_res1 : g_res0;
    float*       res_out = parity ? g_res0 : g_res1;
    const float* wg   = g_wg  + (size_t)blk * (320 * 240);
    const float* wsr  = g_wsr + (size_t)blk * (120 * 360);
    const float* bg   = g_bg  + blk * 240;
    const float* bsk  = b_skip_all + blk * 240;
    const float* bre  = b_res_all  + blk * 120;

    const int b   = blockIdx.y;
    const int t0  = blockIdx.x << 6;
    const int tid = threadIdx.x;

    const float* resb  = res_in + (size_t)b * 120 * L_LEN;
    const float* condb = g_cond + (size_t)b * 80  * L_LEN;

    for (int idx = tid; idx < 120 * 64; idx += 256) {
        int r = idx >> 6, tt = idx & 63;
        int t = t0 + tt;
        Xs[idx]            = (t >= d) ? resb[r * L_LEN + (t - d)] : 0.f;
        Xs[120 * 64 + idx] = resb[r * L_LEN + t];
    }
    for (int idx = tid; idx < 80 * 64; idx += 256) {
        int m = idx >> 6, tt = idx & 63;
        Xs[240 * 64 + idx] = condb[m * L_LEN + t0 + tt];
    }

    const int ty = tid >> 3;
    const int c0 = (tid & 7) << 3;

    float acc[8][8];
#pragma unroll
    for (int a = 0; a < 8; a++)
#pragma unroll
        for (int c = 0; c < 8; c++) acc[a][c] = 0.f;

    // ---- Phase A: gated(240 x 64) = Wg(240 x 320) * X(320 x 64) ----
    // thread ty<30 owns rows {ty*4..+3} (f half) and {120+ty*4..+3} (g half)
    for (int k0 = 0; k0 < 320; k0 += 16) {
        __syncthreads();
        const float* src = wg + k0 * 240;
#pragma unroll
        for (int it = 0, idx = tid; it < 15; it++, idx += 256) Ws[idx] = src[idx];
        __syncthreads();
        if (ty < 30) {
#pragma unroll
            for (int k = 0; k < 16; k++) {
                const float* wr = Ws + k * 240;
                float4 wlo = *(const float4*)(wr + ty * 4);
                float4 whi = *(const float4*)(wr + 120 + ty * 4);
                const float* xr = Xs + (k0 + k) * 64 + c0;
                float4 xa = *(const float4*)xr;
                float4 xb = *(const float4*)(xr + 4);
                float xv[8] = {xa.x, xa.y, xa.z, xa.w, xb.x, xb.y, xb.z, xb.w};
                float wl[4] = {wlo.x, wlo.y, wlo.z, wlo.w};
                float wh[4] = {whi.x, whi.y, whi.z, whi.w};
#pragma unroll
                for (int a = 0; a < 4; a++)
#pragma unroll
                    for (int c = 0; c < 8; c++) {
                        acc[a][c]     = fmaf(wl[a], xv[c], acc[a][c]);
                        acc[4 + a][c] = fmaf(wh[a], xv[c], acc[4 + a][c]);
                    }
            }
        }
    }
    __syncthreads();

    // activation: z = tanh(f)*sigmoid(g), written into Xs rows 0..119
    if (ty < 30) {
#pragma unroll
        for (int a = 0; a < 4; a++) {
            int r = ty * 4 + a;
            float bl = bg[r], bh = bg[120 + r];
#pragma unroll
            for (int c = 0; c < 8; c++) {
                float f = acc[a][c] + bl;
                float g = acc[4 + a][c] + bh;
                float zz = tanhf(f) * (1.f / (1.f + expf(-g)));
                Xs[r * 64 + c0 + c] = zz;
            }
        }
    }
    __syncthreads();

    // ---- Phase B: [skip(240); res(120)](360 x 64) = Wsr(360 x 120) * z(120 x 64) ----
    float* skipsb = g_skip + (size_t)b * 240 * L_LEN;
    float* resob  = res_out + (size_t)b * 120 * L_LEN;
    const float* rescur = Xs + 120 * 64;   // res(t) still intact in rows 120..239

    for (int pass = 0; pass < 2; pass++) {
        const int rowbase = pass * 256 + ty * 8;
        const bool act = rowbase < 360;
#pragma unroll
        for (int a = 0; a < 8; a++)
#pragma unroll
            for (int c = 0; c < 8; c++) acc[a][c] = 0.f;

        for (int k0 = 0; k0 < 120; k0 += 12) {
            __syncthreads();
            const float* src = wsr + k0 * 360;
            for (int idx = tid; idx < 12 * 360; idx += 256) Ws[idx] = src[idx];
            __syncthreads();
            if (act) {
#pragma unroll
                for (int k = 0; k < 12; k++) {
                    const float* wr = Ws + k * 360 + rowbase;
                    float4 w0 = *(const float4*)wr;
                    float4 w1 = *(const float4*)(wr + 4);
                    const float* xr = Xs + (k0 + k) * 64 + c0;
                    float4 xa = *(const float4*)xr;
                    float4 xb = *(const float4*)(xr + 4);
                    float xv[8] = {xa.x, xa.y, xa.z, xa.w, xb.x, xb.y, xb.z, xb.w};
                    float wv[8] = {w0.x, w0.y, w0.z, w0.w, w1.x, w1.y, w1.z, w1.w};
#pragma unroll
                    for (int a = 0; a < 8; a++)
#pragma unroll
                        for (int c = 0; c < 8; c++)
                            acc[a][c] = fmaf(wv[a], xv[c], acc[a][c]);
                }
            }
        }
        if (act) {
#pragma unroll
            for (int a = 0; a < 8; a++) {
                int orow = rowbase + a;
                if (orow < 240) {
                    float bs = bsk[orow];
                    size_t base = (size_t)orow * L_LEN + t0 + c0;
#pragma unroll
                    for (int c = 0; c < 8; c++) {
                        float old = first ? 0.f : skipsb[base + c];
                        skipsb[base + c] = old + acc[a][c] + bs;
                    }
                } else {
                    int r = orow - 240;
                    float br = bre[r];
                    size_t base = (size_t)r * L_LEN + t0 + c0;
#pragma unroll
                    for (int c = 0; c < 8; c++)
                        resob[base + c] = rescur[r * 64 + c0 + c] + acc[a][c] + br;
                }
            }
        }
    }
}

// ---------------- head: out(256 x T) = W(256 x K) * relu(X(K x T)) + bias ----------------
__global__ void __launch_bounds__(256, 2) head_kernel(const float* __restrict__ bias,
                                                      float* __restrict__ out_param, int which)
{
    extern __shared__ float sm[];
    float* Xs = sm;                 // Kdim*64
    float* Ws = sm + 256 * 64;      // 16*256

    const int Kdim = which ? 256 : 240;
    const float* X  = which ? g_h   : g_skip;
    const float* Wt = which ? g_wh2 : g_wh1;
    float* out = which ? out_param : g_h;

    const int b = blockIdx.y;
    const int t0 = blockIdx.x << 6;
    const int tid = threadIdx.x;

    const float* xb = X + (size_t)b * Kdim * L_LEN;
    for (int idx = tid; idx < Kdim * 64; idx += 256) {
        int k = idx >> 6, tt = idx & 63;
        float v = xb[k * L_LEN + t0 + tt];
        Xs[idx] = v > 0.f ? v : 0.f;
    }

    const int r0 = (tid >> 3) << 3;
    const int c0 = (tid & 7) << 3;
    float acc[8][8];
#pragma unroll
    for (int a = 0; a < 8; a++)
#pragma unroll
        for (int c = 0; c < 8; c++) acc[a][c] = 0.f;

    for (int k0 = 0; k0 < Kdim; k0 += 16) {
        __syncthreads();
        const float* src = Wt + k0 * 256;
#pragma unroll
        for (int it = 0, idx = tid; it < 16; it++, idx += 256) Ws[idx] = src[idx];
        __syncthreads();
#pragma unroll
        for (int k = 0; k < 16; k++) {
            const float* wr = Ws + k * 256 + r0;
            float4 w0 = *(const float4*)wr;
            float4 w1 = *(const float4*)(wr + 4);
            const float* xr = Xs + (k0 + k) * 64 + c0;
            float4 xa = *(const float4*)xr;
            float4 xb4 = *(const float4*)(xr + 4);
            float xv[8] = {xa.x, xa.y, xa.z, xa.w, xb4.x, xb4.y, xb4.z, xb4.w};
            float wv[8] = {w0.x, w0.y, w0.z, w0.w, w1.x, w1.y, w1.z, w1.w};
#pragma unroll
            for (int a = 0; a < 8; a++)
#pragma unroll
                for (int c = 0; c < 8; c++)
                    acc[a][c] = fmaf(wv[a], xv[c], acc[a][c]);
        }
    }
    float* ob = out + (size_t)b * 256 * L_LEN;
#pragma unroll
    for (int a = 0; a < 8; a++) {
        float bb = bias[r0 + a];
        size_t base = (size_t)(r0 + a) * L_LEN + t0 + c0;
#pragma unroll
        for (int c = 0; c < 8; c++) ob[base + c] = acc[a][c] + bb;
    }
}

// ---------------- launcher ----------------
extern "C" void kernel_launch(void* const* d_in, const int* in_sizes, int n_in,
                              void* d_out, int out_size)
{
    const float* wav    = (const float*)d_in[0];
    const float* mel    = (const float*)d_in[1];
    const float* w_up   = (const float*)d_in[2];
    const float* b_up   = (const float*)d_in[3];
    const float* w_in   = (const float*)d_in[4];
    const float* b_in   = (const float*)d_in[5];
    const float* w_gate = (const float*)d_in[6];
    const float* b_gate = (const float*)d_in[7];
    const float* w_cond = (const float*)d_in[8];
    const float* b_cond = (const float*)d_in[9];
    const float* w_res  = (const float*)d_in[10];
    const float* b_res  = (const float*)d_in[11];
    const float* w_skip = (const float*)d_in[12];
    const float* b_skip = (const float*)d_in[13];
    const float* w_h1   = (const float*)d_in[14];
    const float* b_h1   = (const float*)d_in[15];
    const float* w_h2   = (const float*)d_in[16];
    const float* b_h2   = (const float*)d_in[17];
    float* out = (float*)d_out;

    const int SMEM_BLOCK = (320 * 64 + 12 * 360) * 4;        // 99200
    const int SMEM_HEAD  = (256 * 64 + 16 * 256) * 4;        // 81920
    const int SMEM_UP    = (4 * 80 * 68 + 4 * 80 * 80) * 4;  // 189440

    cudaFuncSetAttribute(block_kernel,    cudaFuncAttributeMaxDynamicSharedMemorySize, SMEM_BLOCK);
    cudaFuncSetAttribute(head_kernel,     cudaFuncAttributeMaxDynamicSharedMemorySize, SMEM_HEAD);
    cudaFuncSetAttribute(upsample_kernel, cudaFuncAttributeMaxDynamicSharedMemorySize, SMEM_UP);

    prep_kernel<<<2048, 256>>>(w_gate, b_gate, w_cond, b_cond, w_res, w_skip, w_h1, w_h2);
    upsample_kernel<<<256, 256, SMEM_UP>>>(mel, w_up, b_up);
    init_kernel<<<4096, 256>>>(wav, w_in, b_in);

    dim3 grid(NTILE, 4);
    for (int i = 0; i < 16; i++)
        block_kernel<<<grid, 256, SMEM_BLOCK>>>(b_skip, b_res, i, 1 << (i & 7),
                                                (i == 0) ? 1 : 0, i & 1);

    head_kernel<<<grid, 256, SMEM_HEAD>>>(b_h1, out, 0);
    head_kernel<<<grid, 256, SMEM_HEAD>>>(b_h2, out, 1);
}

// round 2
// speedup vs baseline: 1.0003x; 1.0003x over previous
#include <cuda_runtime.h>
#include <math.h>

#define L_LEN 15872
#define NTILE 248          // L / 64

// ---------------- device scratch (static allocation is allowed) ----------------
__device__ float g_cond[4 * 80 * L_LEN];
__device__ float g_res0[4 * 120 * L_LEN];
__device__ float g_res1[4 * 120 * L_LEN];
__device__ float g_skip[4 * 240 * L_LEN];
__device__ float g_h[4 * 256 * L_LEN];

__device__ float g_wg [16 * 320 * 240];   // [blk][kin][cout]  kin: 0-119 res(t-d), 120-239 res(t), 240-319 cond
__device__ float g_wsr[16 * 120 * 360];   // [blk][r][orow]    orow: 0-239 skip, 240-359 res
__device__ float g_wh1[240 * 256];        // [k][co]
__device__ float g_wh2[256 * 256];        // [k][co]
__device__ float g_bg [16 * 240];         // b_gate + b_cond

// ---------------- weight preparation (transpose into GEMM layouts) ----------------
__global__ void prep_kernel(const float* __restrict__ w_gate, const float* __restrict__ b_gate,
                            const float* __restrict__ w_cond, const float* __restrict__ b_cond,
                            const float* __restrict__ w_res,  const float* __restrict__ w_skip,
                            const float* __restrict__ w_h1,   const float* __restrict__ w_h2)
{
    const int n1 = 16 * 320 * 240;
    const int n2 = 16 * 120 * 360;
    const int n3 = 240 * 256;
    const int n4 = 256 * 256;
    const int n5 = 16 * 240;
    const int total = n1 + n2 + n3 + n4 + n5;
    for (int idx = blockIdx.x * blockDim.x + threadIdx.x; idx < total;
         idx += gridDim.x * blockDim.x) {
        int i2 = idx;
        if (i2 < n1) {
            int blk = i2 / (320 * 240);
            int rem = i2 % (320 * 240);
            int kin = rem / 240, c = rem % 240;
            float v;
            if (kin < 120)       v = w_gate[(((blk * 240) + c) * 120 + kin) * 2 + 0];
            else if (kin < 240)  v = w_gate[(((blk * 240) + c) * 120 + (kin - 120)) * 2 + 1];
            else                 v = w_cond[((blk * 240) + c) * 80 + (kin - 240)];
            g_wg[i2] = v;
        } else if ((i2 -= n1) < n2) {
            int blk = i2 / (120 * 360);
            int rem = i2 % (120 * 360);
            int r = rem / 360, orow = rem % 360;
            float v = (orow < 240) ? w_skip[((blk * 240) + orow) * 120 + r]
                                   : w_res [((blk * 120) + (orow - 240)) * 120 + r];
            g_wsr[i2] = v;
        } else if ((i2 -= n2) < n3) {
            int k = i2 / 256, co = i2 % 256;
            g_wh1[i2] = w_h1[co * 240 + k];
        } else if ((i2 -= n3) < n4) {
            int k = i2 / 256, co = i2 % 256;
            g_wh2[i2] = w_h2[co * 256 + k];
        } else {
            i2 -= n4;
            g_bg[i2] = b_gate[i2] + b_cond[i2];
        }
    }
}

// ---------------- residual init: res0[b,r,t] = w_in[r]*wav[b,t]+b_in[r] ----------------
__global__ void init_kernel(const float* __restrict__ wav, const float* __restrict__ w_in,
                            const float* __restrict__ b_in)
{
    const int total = 4 * 120 * L_LEN;
    for (int idx = blockIdx.x * blockDim.x + threadIdx.x; idx < total;
         idx += gridDim.x * blockDim.x) {
        int t = idx % L_LEN;
        int br = idx / L_LEN;
        int r = br % 120, b = br / 120;
        g_res0[idx] = w_in[r] * wav[b * L_LEN + t] + b_in[r];
    }
}

// ---------------- transposed-conv upsample, phase-structured ----------------
// cond[b,o,256u+p] = b_up[o] + sum_{v,m} mel[b,m,u-v] * w_up[m,o,400+p+256v],  v in {-2..1}
__global__ void __launch_bounds__(256) upsample_kernel(const float* __restrict__ mel,
                                                       const float* __restrict__ w_up,
                                                       const float* __restrict__ b_up)
{
    extern __shared__ float sm[];
    float* mel_s = sm;                 // [4][80][68], index j+1, zero-padded
    float* ws    = sm + 4 * 80 * 68;   // [4 v][80 m][80 o]

    const int p = blockIdx.x;
    const int tid = threadIdx.x;

    for (int idx = tid; idx < 4 * 80 * 68; idx += 256) mel_s[idx] = 0.f;
    __syncthreads();
    for (int idx = tid; idx < 4 * 80 * 63; idx += 256) {
        int j = idx % 63;
        int bm = idx / 63;
        mel_s[bm * 68 + j + 1] = mel[idx];
    }
    bool valid[4];
#pragma unroll
    for (int v = 0; v < 4; v++) {
        int kk = 400 + p + 256 * (v - 2);
        valid[v] = (kk >= 0) && (kk < 800);
        if (valid[v]) {
            for (int idx = tid; idx < 6400; idx += 256) {
                int m = idx / 80, o = idx % 80;
                ws[(v * 80 + m) * 80 + o] = w_up[(m * 80 + o) * 800 + kk];
            }
        }
    }
    __syncthreads();

    for (int tile = tid; tile < 320; tile += 256) {
        int og = tile >> 5;           // 0..9
        int b  = (tile >> 3) & 3;
        int ug = tile & 7;
        int o0 = og * 8, u0 = ug * 8;
        float acc[8][8];
#pragma unroll
        for (int a = 0; a < 8; a++)
#pragma unroll
            for (int c = 0; c < 8; c++) acc[a][c] = 0.f;

        const float* msb = mel_s + b * 80 * 68;
#pragma unroll
        for (int v = 0; v < 4; v++) {
            if (!valid[v]) continue;
            int vv = v - 2;
#pragma unroll 4
            for (int m = 0; m < 80; m++) {
                const float* wr = ws + (v * 80 + m) * 80 + o0;
                float4 wA = *(const float4*)wr;
                float4 wB = *(const float4*)(wr + 4);
                float wv[8] = {wA.x, wA.y, wA.z, wA.w, wB.x, wB.y, wB.z, wB.w};
                const float* xr = msb + m * 68 + (u0 - vv) + 1;
                float xv[8];
#pragma unroll
                for (int c = 0; c < 8; c++) xv[c] = xr[c];
#pragma unroll
                for (int a = 0; a < 8; a++)
#pragma unroll
                    for (int c = 0; c < 8; c++)
                        acc[a][c] = fmaf(wv[a], xv[c], acc[a][c]);
            }
        }
#pragma unroll
        for (int a = 0; a < 8; a++) {
            float bo = b_up[o0 + a];
#pragma unroll
            for (int c = 0; c < 8; c++) {
                int u = u0 + c;
                if (u < 62)
                    g_cond[((size_t)b * 80 + o0 + a) * L_LEN + 256 * u + p] = acc[a][c] + bo;
            }
        }
    }
}

// ---------------- fused residual block: gated GEMM + activation + skip/res GEMM ----------------
__global__ void __launch_bounds__(256, 2) block_kernel(const float* __restrict__ b_skip_all,
                                                       const float* __restrict__ b_res_all,
                                                       int blk, int d, int first, int parity)
{
    extern __shared__ float sm[];
    float* Xs = sm;                    // 320*64 inputs; rows 0-119 become z after phase A
    float* Ws = sm + 320 * 64;         // weight chunk, up to 12*360

    const float* res_in  = parity ? g_res1 : g_res0;
    float*       res_out = parity ? g_res0 : g_res1;
    const float* wg   = g_wg  + (size_t)blk * (320 * 240);
    const float* wsr  = g_wsr + (size_t)blk * (120 * 360);
    const float* bg   = g_bg  + blk * 240;
    const float* bsk  = b_skip_all + blk * 240;
    const float* bre  = b_res_all  + blk * 120;

    const int b   = blockIdx.y;
    const int t0  = blockIdx.x << 6;
    const int tid = threadIdx.x;

    const float* resb  = res_in + (size_t)b * 120 * L_LEN;
    const float* condb = g_cond + (size_t)b * 80  * L_LEN;

    for (int idx = tid; idx < 120 * 64; idx += 256) {
        int r = idx >> 6, tt = idx & 63;
        int t = t0 + tt;
        Xs[idx]            = (t >= d) ? resb[r * L_LEN + (t - d)] : 0.f;
        Xs[120 * 64 + idx] = resb[r * L_LEN + t];
    }
    for (int idx = tid; idx < 80 * 64; idx += 256) {
        int m = idx >> 6, tt = idx & 63;
        Xs[240 * 64 + idx] = condb[m * L_LEN + t0 + tt];
    }

    const int ty = tid >> 3;
    const int c0 = (tid & 7) << 3;

    float acc[8][8];
#pragma unroll
    for (int a = 0; a < 8; a++)
#pragma unroll
        for (int c = 0; c < 8; c++) acc[a][c] = 0.f;

    // ---- Phase A: gated(240 x 64) = Wg(240 x 320) * X(320 x 64) ----
    // thread ty<30 owns rows {ty*4..+3} (f half) and {120+ty*4..+3} (g half)
    for (int k0 = 0; k0 < 320; k0 += 16) {
        __syncthreads();
        const float* src = wg + k0 * 240;
#pragma unroll
        for (int it = 0, idx = tid; it < 15; it++, idx += 256) Ws[idx] = src[idx];
        __syncthreads();
        if (ty < 30) {
#pragma unroll
            for (int k = 0; k < 16; k++) {
                const float* wr = Ws + k * 240;
                float4 wlo = *(const float4*)(wr + ty * 4);
                float4 whi = *(const float4*)(wr + 120 + ty * 4);
                const float* xr = Xs + (k0 + k) * 64 + c0;
                float4 xa = *(const float4*)xr;
                float4 xb = *(const float4*)(xr + 4);
                float xv[8] = {xa.x, xa.y, xa.z, xa.w, xb.x, xb.y, xb.z, xb.w};
                float wl[4] = {wlo.x, wlo.y, wlo.z, wlo.w};
                float wh[4] = {whi.x, whi.y, whi.z, whi.w};
#pragma unroll
                for (int a = 0; a < 4; a++)
#pragma unroll
                    for (int c = 0; c < 8; c++) {
                        acc[a][c]     = fmaf(wl[a], xv[c], acc[a][c]);
                        acc[4 + a][c] = fmaf(wh[a], xv[c], acc[4 + a][c]);
                    }
            }
        }
    }
    __syncthreads();

    // activation: z = tanh(f)*sigmoid(g), written into Xs rows 0..119
    if (ty < 30) {
#pragma unroll
        for (int a = 0; a < 4; a++) {
            int r = ty * 4 + a;
            float bl = bg[r], bh = bg[120 + r];
#pragma unroll
            for (int c = 0; c < 8; c++) {
                float f = acc[a][c] + bl;
                float g = acc[4 + a][c] + bh;
                float zz = tanhf(f) * (1.f / (1.f + expf(-g)));
                Xs[r * 64 + c0 + c] = zz;
            }
        }
    }
    __syncthreads();

    // ---- Phase B: [skip(240); res(120)](360 x 64) = Wsr(360 x 120) * z(120 x 64) ----
    float* skipsb = g_skip + (size_t)b * 240 * L_LEN;
    float* resob  = res_out + (size_t)b * 120 * L_LEN;
    const float* rescur = Xs + 120 * 64;   // res(t) still intact in rows 120..239

    for (int pass = 0; pass < 2; pass++) {
        const int rowbase = pass * 256 + ty * 8;
        const bool act = rowbase < 360;
#pragma unroll
        for (int a = 0; a < 8; a++)
#pragma unroll
            for (int c = 0; c < 8; c++) acc[a][c] = 0.f;

        for (int k0 = 0; k0 < 120; k0 += 12) {
            __syncthreads();
            const float* src = wsr + k0 * 360;
            for (int idx = tid; idx < 12 * 360; idx += 256) Ws[idx] = src[idx];
            __syncthreads();
            if (act) {
#pragma unroll
                for (int k = 0; k < 12; k++) {
                    const float* wr = Ws + k * 360 + rowbase;
                    float4 w0 = *(const float4*)wr;
                    float4 w1 = *(const float4*)(wr + 4);
                    const float* xr = Xs + (k0 + k) * 64 + c0;
                    float4 xa = *(const float4*)xr;
                    float4 xb = *(const float4*)(xr + 4);
                    float xv[8] = {xa.x, xa.y, xa.z, xa.w, xb.x, xb.y, xb.z, xb.w};
                    float wv[8] = {w0.x, w0.y, w0.z, w0.w, w1.x, w1.y, w1.z, w1.w};
#pragma unroll
                    for (int a = 0; a < 8; a++)
#pragma unroll
                        for (int c = 0; c < 8; c++)
                            acc[a][c] = fmaf(wv[a], xv[c], acc[a][c]);
                }
            }
        }
        if (act) {
#pragma unroll
            for (int a = 0; a < 8; a++) {
                int orow = rowbase + a;
                if (orow < 240) {
                    float bs = bsk[orow];
                    size_t base = (size_t)orow * L_LEN + t0 + c0;
#pragma unroll
                    for (int c = 0; c < 8; c++) {
                        float old = first ? 0.f : skipsb[base + c];
                        skipsb[base + c] = old + acc[a][c] + bs;
                    }
                } else {
                    int r = orow - 240;
                    float br = bre[r];
                    size_t base = (size_t)r * L_LEN + t0 + c0;
#pragma unroll
                    for (int c = 0; c < 8; c++)
                        resob[base + c] = rescur[r * 64 + c0 + c] + acc[a][c] + br;
                }
            }
        }
    }
}

// ---------------- head: out(256 x T) = W(256 x K) * relu(X(K x T)) + bias ----------------
__global__ void __launch_bounds__(256, 2) head_kernel(const float* __restrict__ bias,
                                                      float* __restrict__ out_param, int which)
{
    extern __shared__ float sm[];
    float* Xs = sm;                 // Kdim*64
    float* Ws = sm + 256 * 64;      // 16*256

    const int Kdim = which ? 256 : 240;
    const float* X  = which ? g_h   : g_skip;
    const float* Wt = which ? g_wh2 : g_wh1;
    float* out = which ? out_param : g_h;

    const int b = blockIdx.y;
    const int t0 = blockIdx.x << 6;
    const int tid = threadIdx.x;

    const float* xb = X + (size_t)b * Kdim * L_LEN;
    for (int idx = tid; idx < Kdim * 64; idx += 256) {
        int k = idx >> 6, tt = idx & 63;
        float v = xb[k * L_LEN + t0 + tt];
        Xs[idx] = v > 0.f ? v : 0.f;
    }

    const int r0 = (tid >> 3) << 3;
    const int c0 = (tid & 7) << 3;
    float acc[8][8];
#pragma unroll
    for (int a = 0; a < 8; a++)
#pragma unroll
        for (int c = 0; c < 8; c++) acc[a][c] = 0.f;

    for (int k0 = 0; k0 < Kdim; k0 += 16) {
        __syncthreads();
        const float* src = Wt + k0 * 256;
#pragma unroll
        for (int it = 0, idx = tid; it < 16; it++, idx += 256) Ws[idx] = src[idx];
        __syncthreads();
#pragma unroll
        for (int k = 0; k < 16; k++) {
            const float* wr = Ws + k * 256 + r0;
            float4 w0 = *(const float4*)wr;
            float4 w1 = *(const float4*)(wr + 4);
            const float* xr = Xs + (k0 + k) * 64 + c0;
            float4 xa = *(const float4*)xr;
            float4 xb4 = *(const float4*)(xr + 4);
            float xv[8] = {xa.x, xa.y, xa.z, xa.w, xb4.x, xb4.y, xb4.z, xb4.w};
            float wv[8] = {w0.x, w0.y, w0.z, w0.w, w1.x, w1.y, w1.z, w1.w};
#pragma unroll
            for (int a = 0; a < 8; a++)
#pragma unroll
                for (int c = 0; c < 8; c++)
                    acc[a][c] = fmaf(wv[a], xv[c], acc[a][c]);
        }
    }
    float* ob = out + (size_t)b * 256 * L_LEN;
#pragma unroll
    for (int a = 0; a < 8; a++) {
        float bb = bias[r0 + a];
        size_t base = (size_t)(r0 + a) * L_LEN + t0 + c0;
#pragma unroll
        for (int c = 0; c < 8; c++) ob[base + c] = acc[a][c] + bb;
    }
}

// ---------------- launcher ----------------
extern "C" void kernel_launch(void* const* d_in, const int* in_sizes, int n_in,
                              void* d_out, int out_size)
{
    const float* wav    = (const float*)d_in[0];
    const float* mel    = (const float*)d_in[1];
    const float* w_up   = (const float*)d_in[2];
    const float* b_up   = (const float*)d_in[3];
    const float* w_in   = (const float*)d_in[4];
    const float* b_in   = (const float*)d_in[5];
    const float* w_gate = (const float*)d_in[6];
    const float* b_gate = (const float*)d_in[7];
    const float* w_cond = (const float*)d_in[8];
    const float* b_cond = (const float*)d_in[9];
    const float* w_res  = (const float*)d_in[10];
    const float* b_res  = (const float*)d_in[11];
    const float* w_skip = (const float*)d_in[12];
    const float* b_skip = (const float*)d_in[13];
    const float* w_h1   = (const float*)d_in[14];
    const float* b_h1   = (const float*)d_in[15];
    const float* w_h2   = (const float*)d_in[16];
    const float* b_h2   = (const float*)d_in[17];
    float* out = (float*)d_out;

    const int SMEM_BLOCK = (320 * 64 + 12 * 360) * 4;        // 99200
    const int SMEM_HEAD  = (256 * 64 + 16 * 256) * 4;        // 81920
    const int SMEM_UP    = (4 * 80 * 68 + 4 * 80 * 80) * 4;  // 189440

    cudaFuncSetAttribute(block_kernel,    cudaFuncAttributeMaxDynamicSharedMemorySize, SMEM_BLOCK);
    cudaFuncSetAttribute(head_kernel,     cudaFuncAttributeMaxDynamicSharedMemorySize, SMEM_HEAD);
    cudaFuncSetAttribute(upsample_kernel, cudaFuncAttributeMaxDynamicSharedMemorySize, SMEM_UP);

    prep_kernel<<<2048, 256>>>(w_gate, b_gate, w_cond, b_cond, w_res, w_skip, w_h1, w_h2);
    upsample_kernel<<<256, 256, SMEM_UP>>>(mel, w_up, b_up);
    init_kernel<<<4096, 256>>>(wav, w_in, b_in);

    dim3 grid(NTILE, 4);
    for (int i = 0; i < 16; i++)
        block_kernel<<<grid, 256, SMEM_BLOCK>>>(b_skip, b_res, i, 1 << (i & 7),
                                                (i == 0) ? 1 : 0, i & 1);

    head_kernel<<<grid, 256, SMEM_HEAD>>>(b_h1, out, 0);
    head_kernel<<<grid, 256, SMEM_HEAD>>>(b_h2, out, 1);
}

// round 6
// speedup vs baseline: 1.0037x; 1.0034x over previous
#include <cuda_runtime.h>
#include <cuda_bf16.h>
#include <math.h>
#include <stdint.h>

#define L_LEN 15872
#define NT64 248

// ---------------- device scratch ----------------
__device__ float g_cond[4 * 80 * L_LEN];
__device__ float g_res0[4 * 120 * L_LEN];
__device__ float g_res1[4 * 120 * L_LEN];
__device__ float g_skip[4 * 240 * L_LEN];
__device__ float g_h[4 * 256 * L_LEN];
__device__ float g_bg[16 * 240];

// extended-K bf16 weights (3-term hi/lo baked into K):
__device__ __align__(1024) __nv_bfloat16 g_W1[16 * 30 * 256 * 40];
__device__ __align__(1024) __nv_bfloat16 g_W2[16 * 12 * 384 * 40];
__device__ __align__(1024) __nv_bfloat16 g_WH1[24 * 256 * 40];
__device__ __align__(1024) __nv_bfloat16 g_WH2[24 * 256 * 40];

// ---------------- helpers ----------------
__device__ __forceinline__ uint32_t smem_u32(const void* p) {
    uint32_t a;
    asm("{ .reg .u64 t; cvta.to.shared.u64 t, %1; cvt.u32.u64 %0, t; }" : "=r"(a) : "l"(p));
    return a;
}
__device__ __forceinline__ void ldmA(uint32_t* a, uint32_t addr) {
    asm volatile("ldmatrix.sync.aligned.m8n8.x4.shared.b16 {%0,%1,%2,%3}, [%4];"
        : "=r"(a[0]), "=r"(a[1]), "=r"(a[2]), "=r"(a[3]) : "r"(addr));
}
__device__ __forceinline__ void ldmB(uint32_t* b, uint32_t addr) {   // non-trans: k contiguous
    asm volatile("ldmatrix.sync.aligned.m8n8.x4.shared.b16 {%0,%1,%2,%3}, [%4];"
        : "=r"(b[0]), "=r"(b[1]), "=r"(b[2]), "=r"(b[3]) : "r"(addr));
}
__device__ __forceinline__ void mma16816(float* c, const uint32_t* a, const uint32_t* b) {
    asm volatile("mma.sync.aligned.m16n8k16.row.col.f32.bf16.bf16.f32 "
        "{%0,%1,%2,%3}, {%4,%5,%6,%7}, {%8,%9}, {%0,%1,%2,%3};"
        : "+f"(c[0]), "+f"(c[1]), "+f"(c[2]), "+f"(c[3])
        : "r"(a[0]), "r"(a[1]), "r"(a[2]), "r"(a[3]), "r"(b[0]), "r"(b[1]));
}
#define CP_ASYNC(dst, src) asm volatile("cp.async.ca.shared.global [%0], [%1], 16;" :: "r"(dst), "l"(src))
#define CP_COMMIT()        asm volatile("cp.async.commit_group;" ::: "memory")
#define CP_WAIT1()         asm volatile("cp.async.wait_group 1;" ::: "memory")
#define CP_WAIT0()         asm volatile("cp.async.wait_group 0;" ::: "memory")

__device__ __forceinline__ __nv_bfloat16 bsel(float v, int term) {
    __nv_bfloat16 h = __float2bfloat16(v);
    if (term < 2) return h;
    return __float2bfloat16(v - __bfloat162float(h));
}
__device__ __forceinline__ float sigmoidf_(float g) {
    return __fdividef(1.f, 1.f + __expf(-g));
}
__device__ __forceinline__ float tanhf_acc(float f) {
    f = fminf(15.f, fmaxf(-15.f, f));
    float e = expm1f(2.f * f);
    return __fdividef(e, e + 2.f);
}

// ---------------- weight prep ----------------
__global__ void prep_kernel(const float* __restrict__ w_gate, const float* __restrict__ b_gate,
                            const float* __restrict__ w_cond, const float* __restrict__ b_cond,
                            const float* __restrict__ w_res,  const float* __restrict__ w_skip,
                            const float* __restrict__ w_h1,   const float* __restrict__ w_h2)
{
    const int NW1 = 16 * 30 * 256 * 40;
    const int NW2 = 16 * 12 * 384 * 40;
    const int NH  = 24 * 256 * 40;
    const int total = NW1 + NW2 + 2 * NH + 16 * 240;
    for (int idx = blockIdx.x * blockDim.x + threadIdx.x; idx < total;
         idx += gridDim.x * blockDim.x) {
        int i = idx;
        if (i < NW1) {
            int blk = i / 307200, r = i % 307200;
            int c2 = r / 10240, r2 = r % 10240;
            int row = r2 / 40, col = r2 % 40;
            int term = c2 / 10;
            int k = (c2 % 10) * 32 + col;
            int T = row >> 4, rr = row & 15;
            int chf = (T << 3) + (rr & 7);
            float v = 0.f;
            if (col < 32 && chf < 120) {
                int gch = (rr < 8) ? chf : (120 + chf);
                if (k < 120)       v = w_gate[((blk * 240 + gch) * 120 + k) * 2];
                else if (k < 240)  v = w_gate[((blk * 240 + gch) * 120 + (k - 120)) * 2 + 1];
                else               v = w_cond[(blk * 240 + gch) * 80 + (k - 240)];
            }
            g_W1[i] = bsel(v, term);
        } else if ((i -= NW1) < NW2) {
            int blk = i / 184320, r = i % 184320;
            int c2 = r / 15360, r2 = r % 15360;
            int row = r2 / 40, col = r2 % 40;
            int term = c2 / 4;
            int k = (c2 % 4) * 32 + col;
            float v = 0.f;
            if (col < 32 && k < 120) {
                if (row < 240)                    v = w_skip[(blk * 240 + row) * 120 + k];
                else if (row >= 256 && row < 376) v = w_res[(blk * 120 + (row - 256)) * 120 + k];
            }
            g_W2[i] = bsel(v, term);
        } else if ((i -= NW2) < NH) {
            int c2 = i / 10240, r2 = i % 10240;
            int row = r2 / 40, col = r2 % 40;
            int term = c2 / 8;
            int k = (c2 % 8) * 32 + col;
            float v = (col < 32 && k < 240) ? w_h1[row * 240 + k] : 0.f;
            g_WH1[i] = bsel(v, term);
        } else if ((i -= NH) < NH) {
            int c2 = i / 10240, r2 = i % 10240;
            int row = r2 / 40, col = r2 % 40;
            int term = c2 / 8;
            int k = (c2 % 8) * 32 + col;
            float v = (col < 32) ? w_h2[row * 256 + k] : 0.f;
            g_WH2[i] = bsel(v, term);
        } else {
            i -= NH;
            g_bg[i] = b_gate[i] + b_cond[i];
        }
    }
}

// ---------------- residual init ----------------
__global__ void init_kernel(const float* __restrict__ wav, const float* __restrict__ w_in,
                            const float* __restrict__ b_in)
{
    const int total = 4 * 120 * L_LEN;
    for (int idx = blockIdx.x * blockDim.x + threadIdx.x; idx < total;
         idx += gridDim.x * blockDim.x) {
        int t = idx % L_LEN;
        int br = idx / L_LEN;
        int r = br % 120, b = br / 120;
        g_res0[idx] = w_in[r] * wav[b * L_LEN + t] + b_in[r];
    }
}

// ---------------- mel upsample (fp32) ----------------
extern __shared__ char dynsmem[];

__global__ void __launch_bounds__(256) upsample_kernel(const float* __restrict__ mel,
                                                       const float* __restrict__ w_up,
                                                       const float* __restrict__ b_up)
{
    float* mel_s = (float*)dynsmem;
    float* ws    = (float*)dynsmem + 4 * 80 * 68;
    const int p = blockIdx.x, tid = threadIdx.x;

    for (int idx = tid; idx < 4 * 80 * 68; idx += 256) mel_s[idx] = 0.f;
    __syncthreads();
    for (int idx = tid; idx < 4 * 80 * 63; idx += 256)
        mel_s[(idx / 63) * 68 + (idx % 63) + 1] = mel[idx];
    bool valid[4];
#pragma unroll
    for (int v = 0; v < 4; v++) {
        int kk = 400 + p + 256 * (v - 2);
        valid[v] = (kk >= 0) && (kk < 800);
        if (valid[v])
            for (int idx = tid; idx < 6400; idx += 256)
                ws[(v * 80 + idx / 80) * 80 + idx % 80] = w_up[((idx / 80) * 80 + idx % 80) * 800 + kk];
    }
    __syncthreads();

    for (int tile = tid; tile < 320; tile += 256) {
        int og = tile >> 5, b = (tile >> 3) & 3, ug = tile & 7;
        int o0 = og * 8, u0 = ug * 8;
        float acc[8][8];
#pragma unroll
        for (int a = 0; a < 8; a++)
#pragma unroll
            for (int c = 0; c < 8; c++) acc[a][c] = 0.f;
        const float* msb = mel_s + b * 80 * 68;
#pragma unroll
        for (int v = 0; v < 4; v++) {
            if (!valid[v]) continue;
            int vv = v - 2;
#pragma unroll 4
            for (int m = 0; m < 80; m++) {
                const float* wr = ws + (v * 80 + m) * 80 + o0;
                float4 wA = *(const float4*)wr;
                float4 wB = *(const float4*)(wr + 4);
                float wv[8] = {wA.x, wA.y, wA.z, wA.w, wB.x, wB.y, wB.z, wB.w};
                const float* xr = msb + m * 68 + (u0 - vv) + 1;
                float xv[8];
#pragma unroll
                for (int c = 0; c < 8; c++) xv[c] = xr[c];
#pragma unroll
                for (int a = 0; a < 8; a++)
#pragma unroll
                    for (int c = 0; c < 8; c++)
                        acc[a][c] = fmaf(wv[a], xv[c], acc[a][c]);
            }
        }
#pragma unroll
        for (int a = 0; a < 8; a++) {
            float bo = b_up[o0 + a];
#pragma unroll
            for (int c = 0; c < 8; c++)
                if (u0 + c < 62)
                    g_cond[((size_t)b * 80 + o0 + a) * L_LEN + 256 * (u0 + c) + p] = acc[a][c] + bo;
        }
    }
}

// ---------------- fused residual block (mma.sync) ----------------
#define XHI 0
#define XLO 44032
#define ZHI 88064
#define ZLO 105472
#define WB0 122880
#define WB1 153600
#define SMEM_BLOCK 184320

__global__ void __launch_bounds__(256, 1) block_kernel(const float* __restrict__ bsk_all,
                                                       const float* __restrict__ brs_all,
                                                       int blk, int d, int first, int parity)
{
    char* smb = dynsmem;
    const uint32_t su = smem_u32(smb);
    const int tid = threadIdx.x, w = tid >> 5, lane = tid & 31;
    const int b = blockIdx.y, t0 = blockIdx.x << 6;

    const float* res_in  = (parity ? g_res1 : g_res0) + (size_t)b * 120 * L_LEN;
    float*       res_out = (parity ? g_res0 : g_res1) + (size_t)b * 120 * L_LEN;
    const float* condb   = g_cond + (size_t)b * 80 * L_LEN;

    const char* W1 = (const char*)(g_W1 + (size_t)blk * 30 * 256 * 40);
    const char* W2 = (const char*)(g_W2 + (size_t)blk * 12 * 384 * 40);

    for (int off = tid * 16; off < 20480; off += 4096) CP_ASYNC(su + WB0 + off, W1 + off);
    CP_COMMIT();
    for (int off = tid * 16; off < 20480; off += 4096) CP_ASYNC(su + WB1 + off, W1 + 20480 + off);
    CP_COMMIT();

    __nv_bfloat16* xh = (__nv_bfloat16*)(smb + XHI);
    __nv_bfloat16* xl = (__nv_bfloat16*)(smb + XLO);
    for (int idx = tid; idx < 320 * 64; idx += 256) {
        int t = idx & 63, k = idx >> 6;
        float v;
        if (k < 120)      { int ts = t0 + t - d; v = (ts >= 0) ? res_in[k * L_LEN + ts] : 0.f; }
        else if (k < 240)   v = res_in[(k - 120) * L_LEN + t0 + t];
        else                v = condb[(k - 240) * L_LEN + t0 + t];
        __nv_bfloat16 h = __float2bfloat16(v);
        xh[t * 344 + k] = h;
        xl[t * 344 + k] = __float2bfloat16(v - __bfloat162float(h));
    }

    float acc[2][8][4];
#pragma unroll
    for (int m = 0; m < 2; m++)
#pragma unroll
        for (int n = 0; n < 8; n++)
#pragma unroll
            for (int q = 0; q < 4; q++) acc[m][n][q] = 0.f;

    int kc = 0;   // c2 % 10
    for (int c2 = 0; c2 < 30; c2++) {
        CP_WAIT1();
        __syncthreads();
        const uint32_t wb = su + ((c2 & 1) ? WB1 : WB0);
        const uint32_t xb = su + ((c2 >= 10 && c2 < 20) ? XLO : XHI);
#pragma unroll
        for (int j = 0; j < 2; j++) {
            uint32_t a[2][4], bf[4][4];
#pragma unroll
            for (int m = 0; m < 2; m++)
                ldmA(a[m], wb + ((((2 * w + m) << 4) + (lane & 15)) * 40 + ((lane >> 4) << 3) + j * 16) * 2);
            const int brow = ((lane & 16) >> 1) + (lane & 7);
            const int bcol = (kc << 5) + j * 16 + (lane & 8);
#pragma unroll
            for (int np = 0; np < 4; np++)
                ldmB(bf[np], xb + (((np << 4) + brow) * 344 + bcol) * 2);
#pragma unroll
            for (int m = 0; m < 2; m++)
#pragma unroll
                for (int nt = 0; nt < 8; nt++)
                    mma16816(acc[m][nt], a[m], &bf[nt >> 1][(nt & 1) << 1]);
        }
        __syncthreads();
        if (c2 + 2 < 30) {
            const char* src = W1 + (size_t)(c2 + 2) * 20480;
            uint32_t dst = su + ((c2 & 1) ? WB1 : WB0);
            for (int off = tid * 16; off < 20480; off += 4096) CP_ASYNC(dst + off, src + off);
        }
        CP_COMMIT();
        if (++kc == 10) kc = 0;
    }
    CP_WAIT0();
    for (int off = tid * 16; off < 30720; off += 4096) CP_ASYNC(su + WB0 + off, W2 + off);
    CP_COMMIT();

    // activation -> z (bf16 hi/lo) [64t][136ch]
    const float* bg = g_bg + blk * 240;
    __nv_bfloat16* zh = (__nv_bfloat16*)(smb + ZHI);
    __nv_bfloat16* zl = (__nv_bfloat16*)(smb + ZLO);
#pragma unroll
    for (int j = 0; j < 2; j++) {
        int ch = ((2 * w + j) << 3) + (lane >> 2);
        bool valid = ch < 120;
        float bf_ = valid ? bg[ch] : 0.f;
        float bg_ = valid ? bg[120 + ch] : 0.f;
#pragma unroll
        for (int nt = 0; nt < 8; nt++) {
            int tt = (nt << 3) + ((lane & 3) << 1);
#pragma unroll
            for (int q = 0; q < 2; q++) {
                float z = 0.f;
                if (valid) {
                    float f = acc[j][nt][q] + bf_;
                    float g = acc[j][nt][2 + q] + bg_;
                    z = tanhf_acc(f) * sigmoidf_(g);
                }
                __nv_bfloat16 h = __float2bfloat16(z);
                zh[(tt + q) * 136 + ch] = h;
                zl[(tt + q) * 136 + ch] = __float2bfloat16(z - __bfloat162float(h));
            }
        }
    }
    for (int off = tid * 16; off < 30720; off += 4096) CP_ASYNC(su + WB1 + off, W2 + 30720 + off);
    CP_COMMIT();
    __syncthreads();

    float ac2[3][8][4];
#pragma unroll
    for (int m = 0; m < 3; m++)
#pragma unroll
        for (int n = 0; n < 8; n++)
#pragma unroll
            for (int q = 0; q < 4; q++) ac2[m][n][q] = 0.f;

    for (int c2 = 0; c2 < 12; c2++) {
        CP_WAIT1();
        __syncthreads();
        const uint32_t wb = su + ((c2 & 1) ? WB1 : WB0);
        const uint32_t zb = su + (((c2 >> 2) == 1) ? ZLO : ZHI);
#pragma unroll
        for (int j = 0; j < 2; j++) {
            uint32_t a[3][4], bf[4][4];
#pragma unroll
            for (int m = 0; m < 3; m++)
                ldmA(a[m], wb + ((((3 * w + m) << 4) + (lane & 15)) * 40 + ((lane >> 4) << 3) + j * 16) * 2);
            const int brow = ((lane & 16) >> 1) + (lane & 7);
            const int bcol = ((c2 & 3) << 5) + j * 16 + (lane & 8);
#pragma unroll
            for (int np = 0; np < 4; np++)
                ldmB(bf[np], zb + (((np << 4) + brow) * 136 + bcol) * 2);
#pragma unroll
            for (int m = 0; m < 3; m++)
#pragma unroll
                for (int nt = 0; nt < 8; nt++)
                    mma16816(ac2[m][nt], a[m], &bf[nt >> 1][(nt & 1) << 1]);
        }
        __syncthreads();
        if (c2 + 2 < 12) {
            const char* src = W2 + (size_t)(c2 + 2) * 30720;
            uint32_t dst = su + ((c2 & 1) ? WB1 : WB0);
            for (int off = tid * 16; off < 30720; off += 4096) CP_ASYNC(dst + off, src + off);
        }
        CP_COMMIT();
    }

    const float* bsk = bsk_all + blk * 240;
    const float* brs = brs_all + blk * 120;
    float* skipb = g_skip + (size_t)b * 240 * L_LEN;
#pragma unroll
    for (int j = 0; j < 3; j++) {
        int mt = 3 * w + j;
#pragma unroll
        for (int h2 = 0; h2 < 2; h2++) {
            int row = (mt << 4) + (lane >> 2) + (h2 << 3);
#pragma unroll
            for (int nt = 0; nt < 8; nt++) {
                int tt = t0 + (nt << 3) + ((lane & 3) << 1);
                float v0 = ac2[j][nt][h2 << 1], v1 = ac2[j][nt][(h2 << 1) + 1];
                if (row < 240) {
                    size_t o = (size_t)row * L_LEN + tt;
                    float bb = bsk[row];
                    if (first) { skipb[o] = v0 + bb; skipb[o + 1] = v1 + bb; }
                    else       { skipb[o] += v0 + bb; skipb[o + 1] += v1 + bb; }
                } else if (row >= 256 && row < 376) {
                    int rc = row - 256;
                    size_t o = (size_t)rc * L_LEN + tt;
                    float bb = brs[rc];
                    res_out[o]     = res_in[o]     + v0 + bb;
                    res_out[o + 1] = res_in[o + 1] + v1 + bb;
                }
            }
        }
    }
}

// ---------------- head GEMM (mma.sync) ----------------
#define HXHI 0
#define HXLO 33792
#define HWB0 67584
#define HWB1 88064
#define SMEM_HEAD 108544

__global__ void __launch_bounds__(256, 2) head_kernel(const float* __restrict__ bias,
                                                      float* __restrict__ outp, int which)
{
    char* smb = dynsmem;
    const uint32_t su = smem_u32(smb);
    const int tid = threadIdx.x, w = tid >> 5, lane = tid & 31;
    const int b = blockIdx.y, t0 = blockIdx.x << 6;

    const int Kreal = which ? 256 : 240;
    const float* srcb = (which ? g_h : g_skip) + (size_t)b * Kreal * L_LEN;
    const char* W = (const char*)(which ? g_WH2 : g_WH1);
    float* out = (which ? outp : g_h) + (size_t)b * 256 * L_LEN;

    for (int off = tid * 16; off < 20480; off += 4096) CP_ASYNC(su + HWB0 + off, W + off);
    CP_COMMIT();
    for (int off = tid * 16; off < 20480; off += 4096) CP_ASYNC(su + HWB1 + off, W + 20480 + off);
    CP_COMMIT();

    __nv_bfloat16* xh = (__nv_bfloat16*)(smb + HXHI);
    __nv_bfloat16* xl = (__nv_bfloat16*)(smb + HXLO);
    for (int idx = tid; idx < 256 * 64; idx += 256) {
        int t = idx & 63, k = idx >> 6;
        float v = (k < Kreal) ? srcb[k * L_LEN + t0 + t] : 0.f;
        v = v > 0.f ? v : 0.f;
        __nv_bfloat16 h = __float2bfloat16(v);
        xh[t * 264 + k] = h;
        xl[t * 264 + k] = __float2bfloat16(v - __bfloat162float(h));
    }

    float acc[2][8][4];
#pragma unroll
    for (int m = 0; m < 2; m++)
#pragma unroll
        for (int n = 0; n < 8; n++)
#pragma unroll
            for (int q = 0; q < 4; q++) acc[m][n][q] = 0.f;

    for (int c2 = 0; c2 < 24; c2++) {
        CP_WAIT1();
        __syncthreads();
        const uint32_t wb = su + ((c2 & 1) ? HWB1 : HWB0);
        const uint32_t xb = su + ((c2 >= 8 && c2 < 16) ? HXLO : HXHI);
#pragma unroll
        for (int j = 0; j < 2; j++) {
            uint32_t a[2][4], bf[4][4];
#pragma unroll
            for (int m = 0; m < 2; m++)
                ldmA(a[m], wb + ((((2 * w + m) << 4) + (lane & 15)) * 40 + ((lane >> 4) << 3) + j * 16) * 2);
            const int brow = ((lane & 16) >> 1) + (lane & 7);
            const int bcol = ((c2 & 7) << 5) + j * 16 + (lane & 8);
#pragma unroll
            for (int np = 0; np < 4; np++)
                ldmB(bf[np], xb + (((np << 4) + brow) * 264 + bcol) * 2);
#pragma unroll
            for (int m = 0; m < 2; m++)
#pragma unroll
                for (int nt = 0; nt < 8; nt++)
                    mma16816(acc[m][nt], a[m], &bf[nt >> 1][(nt & 1) << 1]);
        }
        __syncthreads();
        if (c2 + 2 < 24) {
            const char* src = W + (size_t)(c2 + 2) * 20480;
            uint32_t dst = su + ((c2 & 1) ? HWB1 : HWB0);
            for (int off = tid * 16; off < 20480; off += 4096) CP_ASYNC(dst + off, src + off);
        }
        CP_COMMIT();
    }

#pragma unroll
    for (int j = 0; j < 2; j++) {
#pragma unroll
        for (int h2 = 0; h2 < 2; h2++) {
            int ch = ((2 * w + j) << 4) + (lane >> 2) + (h2 << 3);
            float bb = bias[ch];
#pragma unroll
            for (int nt = 0; nt < 8; nt++) {
                int tt = t0 + (nt << 3) + ((lane & 3) << 1);
                size_t o = (size_t)ch * L_LEN + tt;
                out[o]     = acc[j][nt][h2 << 1] + bb;
                out[o + 1] = acc[j][nt][(h2 << 1) + 1] + bb;
            }
        }
    }
}

// ---------------- launcher ----------------
extern "C" void kernel_launch(void* const* d_in, const int* in_sizes, int n_in,
                              void* d_out, int out_size)
{
    const float* wav    = (const float*)d_in[0];
    const float* mel    = (const float*)d_in[1];
    const float* w_up   = (const float*)d_in[2];
    const float* b_up   = (const float*)d_in[3];
    const float* w_in   = (const float*)d_in[4];
    const float* b_in   = (const float*)d_in[5];
    const float* w_gate = (const float*)d_in[6];
    const float* b_gate = (const float*)d_in[7];
    const float* w_cond = (const float*)d_in[8];
    const float* b_cond = (const float*)d_in[9];
    const float* w_res  = (const float*)d_in[10];
    const float* b_res  = (const float*)d_in[11];
    const float* w_skip = (const float*)d_in[12];
    const float* b_skip = (const float*)d_in[13];
    const float* w_h1   = (const float*)d_in[14];
    const float* b_h1   = (const float*)d_in[15];
    const float* w_h2   = (const float*)d_in[16];
    const float* b_h2   = (const float*)d_in[17];
    float* out = (float*)d_out;

    const int SMEM_UP = (4 * 80 * 68 + 4 * 80 * 80) * 4;
    cudaFuncSetAttribute(block_kernel,    cudaFuncAttributeMaxDynamicSharedMemorySize, SMEM_BLOCK);
    cudaFuncSetAttribute(head_kernel,     cudaFuncAttributeMaxDynamicSharedMemorySize, SMEM_HEAD);
    cudaFuncSetAttribute(upsample_kernel, cudaFuncAttributeMaxDynamicSharedMemorySize, SMEM_UP);

    prep_kernel<<<4096, 256>>>(w_gate, b_gate, w_cond, b_cond, w_res, w_skip, w_h1, w_h2);
    upsample_kernel<<<256, 256, SMEM_UP>>>(mel, w_up, b_up);
    init_kernel<<<4096, 256>>>(wav, w_in, b_in);

    dim3 grid(NT64, 4);
    for (int i = 0; i < 16; i++)
        block_kernel<<<grid, 256, SMEM_BLOCK>>>(b_skip, b_res, i, 1 << (i & 7),
                                                (i == 0) ? 1 : 0, i & 1);

    head_kernel<<<grid, 256, SMEM_HEAD>>>(b_h1, out, 0);
    head_kernel<<<grid, 256, SMEM_HEAD>>>(b_h2, out, 1);
}

// round 7
// speedup vs baseline: 1.0141x; 1.0103x over previous
#include <cuda_runtime.h>
#include <cuda_bf16.h>
#include <math.h>
#include <stdint.h>

#define L_LEN 15872
#define NT64 248

// ---------------- device scratch ----------------
__device__ float g_cond[4 * 80 * L_LEN];
__device__ float g_res0[4 * 120 * L_LEN];
__device__ float g_res1[4 * 120 * L_LEN];
__device__ float g_skip[4 * 240 * L_LEN];
__device__ float g_h[4 * 256 * L_LEN];
__device__ float g_bg[16 * 240];

// extended-K bf16 weights (3-term hi/lo baked into K):
__device__ __align__(1024) __nv_bfloat16 g_W1[16 * 30 * 256 * 40];
__device__ __align__(1024) __nv_bfloat16 g_W2[16 * 12 * 384 * 40];
__device__ __align__(1024) __nv_bfloat16 g_WH1[24 * 256 * 40];
__device__ __align__(1024) __nv_bfloat16 g_WH2[24 * 256 * 40];

// ---------------- helpers ----------------
__device__ __forceinline__ uint32_t smem_u32(const void* p) {
    uint32_t a;
    asm("{ .reg .u64 t; cvta.to.shared.u64 t, %1; cvt.u32.u64 %0, t; }" : "=r"(a) : "l"(p));
    return a;
}
__device__ __forceinline__ void ldmA(uint32_t* a, uint32_t addr) {
    asm volatile("ldmatrix.sync.aligned.m8n8.x4.shared.b16 {%0,%1,%2,%3}, [%4];"
        : "=r"(a[0]), "=r"(a[1]), "=r"(a[2]), "=r"(a[3]) : "r"(addr));
}
__device__ __forceinline__ void ldmB(uint32_t* b, uint32_t addr) {   // non-trans: k contiguous
    asm volatile("ldmatrix.sync.aligned.m8n8.x4.shared.b16 {%0,%1,%2,%3}, [%4];"
        : "=r"(b[0]), "=r"(b[1]), "=r"(b[2]), "=r"(b[3]) : "r"(addr));
}
__device__ __forceinline__ void mma16816(float* c, const uint32_t* a, const uint32_t* b) {
    asm volatile("mma.sync.aligned.m16n8k16.row.col.f32.bf16.bf16.f32 "
        "{%0,%1,%2,%3}, {%4,%5,%6,%7}, {%8,%9}, {%0,%1,%2,%3};"
        : "+f"(c[0]), "+f"(c[1]), "+f"(c[2]), "+f"(c[3])
        : "r"(a[0]), "r"(a[1]), "r"(a[2]), "r"(a[3]), "r"(b[0]), "r"(b[1]));
}
#define CP_ASYNC(dst, src) asm volatile("cp.async.ca.shared.global [%0], [%1], 16;" :: "r"(dst), "l"(src))
#define CP_COMMIT()        asm volatile("cp.async.commit_group;" ::: "memory")
#define CP_WAIT2()         asm volatile("cp.async.wait_group 2;" ::: "memory")
#define CP_WAIT1()         asm volatile("cp.async.wait_group 1;" ::: "memory")
#define CP_WAIT0()         asm volatile("cp.async.wait_group 0;" ::: "memory")

__device__ __forceinline__ __nv_bfloat16 bsel(float v, int term) {
    __nv_bfloat16 h = __float2bfloat16(v);
    if (term < 2) return h;
    return __float2bfloat16(v - __bfloat162float(h));
}
__device__ __forceinline__ float sigmoidf_(float g) {
    return __fdividef(1.f, 1.f + __expf(-g));
}
__device__ __forceinline__ float tanhf_acc(float f) {
    f = fminf(15.f, fmaxf(-15.f, f));
    float e = expm1f(2.f * f);
    return __fdividef(e, e + 2.f);
}

// ---------------- weight prep ----------------
__global__ void prep_kernel(const float* __restrict__ w_gate, const float* __restrict__ b_gate,
                            const float* __restrict__ w_cond, const float* __restrict__ b_cond,
                            const float* __restrict__ w_res,  const float* __restrict__ w_skip,
                            const float* __restrict__ w_h1,   const float* __restrict__ w_h2)
{
    const int NW1 = 16 * 30 * 256 * 40;
    const int NW2 = 16 * 12 * 384 * 40;
    const int NH  = 24 * 256 * 40;
    const int total = NW1 + NW2 + 2 * NH + 16 * 240;
    for (int idx = blockIdx.x * blockDim.x + threadIdx.x; idx < total;
         idx += gridDim.x * blockDim.x) {
        int i = idx;
        if (i < NW1) {
            int blk = i / 307200, r = i % 307200;
            int c2 = r / 10240, r2 = r % 10240;
            int row = r2 / 40, col = r2 % 40;
            int term = c2 / 10;
            int k = (c2 % 10) * 32 + col;
            int T = row >> 4, rr = row & 15;
            int chf = (T << 3) + (rr & 7);
            float v = 0.f;
            if (col < 32 && chf < 120) {
                int gch = (rr < 8) ? chf : (120 + chf);
                if (k < 120)       v = w_gate[((blk * 240 + gch) * 120 + k) * 2];
                else if (k < 240)  v = w_gate[((blk * 240 + gch) * 120 + (k - 120)) * 2 + 1];
                else               v = w_cond[(blk * 240 + gch) * 80 + (k - 240)];
            }
            g_W1[i] = bsel(v, term);
        } else if ((i -= NW1) < NW2) {
            int blk = i / 184320, r = i % 184320;
            int c2 = r / 15360, r2 = r % 15360;
            int row = r2 / 40, col = r2 % 40;
            int term = c2 / 4;
            int k = (c2 % 4) * 32 + col;
            float v = 0.f;
            if (col < 32 && k < 120) {
                if (row < 240)                    v = w_skip[(blk * 240 + row) * 120 + k];
                else if (row >= 256 && row < 376) v = w_res[(blk * 120 + (row - 256)) * 120 + k];
            }
            g_W2[i] = bsel(v, term);
        } else if ((i -= NW2) < NH) {
            int c2 = i / 10240, r2 = i % 10240;
            int row = r2 / 40, col = r2 % 40;
            int term = c2 / 8;
            int k = (c2 % 8) * 32 + col;
            float v = (col < 32 && k < 240) ? w_h1[row * 240 + k] : 0.f;
            g_WH1[i] = bsel(v, term);
        } else if ((i -= NH) < NH) {
            int c2 = i / 10240, r2 = i % 10240;
            int row = r2 / 40, col = r2 % 40;
            int term = c2 / 8;
            int k = (c2 % 8) * 32 + col;
            float v = (col < 32) ? w_h2[row * 256 + k] : 0.f;
            g_WH2[i] = bsel(v, term);
        } else {
            i -= NH;
            g_bg[i] = b_gate[i] + b_cond[i];
        }
    }
}

// ---------------- residual init ----------------
__global__ void init_kernel(const float* __restrict__ wav, const float* __restrict__ w_in,
                            const float* __restrict__ b_in)
{
    const int total = 4 * 120 * L_LEN;
    for (int idx = blockIdx.x * blockDim.x + threadIdx.x; idx < total;
         idx += gridDim.x * blockDim.x) {
        int t = idx % L_LEN;
        int br = idx / L_LEN;
        int r = br % 120, b = br / 120;
        g_res0[idx] = w_in[r] * wav[b * L_LEN + t] + b_in[r];
    }
}

// ---------------- mel upsample (fp32) ----------------
extern __shared__ char dynsmem[];

__global__ void __launch_bounds__(256) upsample_kernel(const float* __restrict__ mel,
                                                       const float* __restrict__ w_up,
                                                       const float* __restrict__ b_up)
{
    float* mel_s = (float*)dynsmem;
    float* ws    = (float*)dynsmem + 4 * 80 * 68;
    const int p = blockIdx.x, tid = threadIdx.x;

    for (int idx = tid; idx < 4 * 80 * 68; idx += 256) mel_s[idx] = 0.f;
    __syncthreads();
    for (int idx = tid; idx < 4 * 80 * 63; idx += 256)
        mel_s[(idx / 63) * 68 + (idx % 63) + 1] = mel[idx];
    bool valid[4];
#pragma unroll
    for (int v = 0; v < 4; v++) {
        int kk = 400 + p + 256 * (v - 2);
        valid[v] = (kk >= 0) && (kk < 800);
        if (valid[v])
            for (int idx = tid; idx < 6400; idx += 256)
                ws[(v * 80 + idx / 80) * 80 + idx % 80] = w_up[((idx / 80) * 80 + idx % 80) * 800 + kk];
    }
    __syncthreads();

    for (int tile = tid; tile < 320; tile += 256) {
        int og = tile >> 5, b = (tile >> 3) & 3, ug = tile & 7;
        int o0 = og * 8, u0 = ug * 8;
        float acc[8][8];
#pragma unroll
        for (int a = 0; a < 8; a++)
#pragma unroll
            for (int c = 0; c < 8; c++) acc[a][c] = 0.f;
        const float* msb = mel_s + b * 80 * 68;
#pragma unroll
        for (int v = 0; v < 4; v++) {
            if (!valid[v]) continue;
            int vv = v - 2;
#pragma unroll 4
            for (int m = 0; m < 80; m++) {
                const float* wr = ws + (v * 80 + m) * 80 + o0;
                float4 wA = *(const float4*)wr;
                float4 wB = *(const float4*)(wr + 4);
                float wv[8] = {wA.x, wA.y, wA.z, wA.w, wB.x, wB.y, wB.z, wB.w};
                const float* xr = msb + m * 68 + (u0 - vv) + 1;
                float xv[8];
#pragma unroll
                for (int c = 0; c < 8; c++) xv[c] = xr[c];
#pragma unroll
                for (int a = 0; a < 8; a++)
#pragma unroll
                    for (int c = 0; c < 8; c++)
                        acc[a][c] = fmaf(wv[a], xv[c], acc[a][c]);
            }
        }
#pragma unroll
        for (int a = 0; a < 8; a++) {
            float bo = b_up[o0 + a];
#pragma unroll
            for (int c = 0; c < 8; c++)
                if (u0 + c < 62)
                    g_cond[((size_t)b * 80 + o0 + a) * L_LEN + 256 * (u0 + c) + p] = acc[a][c] + bo;
        }
    }
}

// ---------------- fused residual block (mma.sync, deep pipeline) ----------------
#define XHI 0
#define XLO 44032
#define ZHI 88064
#define ZLO 105472
#define WQ  122880
#define SMEM_BLOCK 215040   // WQ + max(4*20480, 3*30720)

__global__ void __launch_bounds__(256, 1) block_kernel(const float* __restrict__ bsk_all,
                                                       const float* __restrict__ brs_all,
                                                       int blk, int d, int first, int parity)
{
    char* smb = dynsmem;
    const uint32_t su = smem_u32(smb);
    const int tid = threadIdx.x, w = tid >> 5, lane = tid & 31;
    const int b = blockIdx.y, t0 = blockIdx.x << 6;

    const float* res_in  = (parity ? g_res1 : g_res0) + (size_t)b * 120 * L_LEN;
    float*       res_out = (parity ? g_res0 : g_res1) + (size_t)b * 120 * L_LEN;
    const float* condb   = g_cond + (size_t)b * 80 * L_LEN;

    const char* W1 = (const char*)(g_W1 + (size_t)blk * 30 * 256 * 40);
    const char* W2 = (const char*)(g_W2 + (size_t)blk * 12 * 384 * 40);

    // GEMM1 prologue: prefetch chunks 0..2 into bufs 0..2
    for (int c = 0; c < 3; c++) {
        for (int off = tid * 16; off < 20480; off += 4096)
            CP_ASYNC(su + WQ + c * 20480 + off, W1 + (size_t)c * 20480 + off);
        CP_COMMIT();
    }

    // stage X: [64t][320k] fp32 -> bf16 hi/lo
    __nv_bfloat16* xh = (__nv_bfloat16*)(smb + XHI);
    __nv_bfloat16* xl = (__nv_bfloat16*)(smb + XLO);
    for (int idx = tid; idx < 320 * 64; idx += 256) {
        int t = idx & 63, k = idx >> 6;
        float v;
        if (k < 120)      { int ts = t0 + t - d; v = (ts >= 0) ? res_in[k * L_LEN + ts] : 0.f; }
        else if (k < 240)   v = res_in[(k - 120) * L_LEN + t0 + t];
        else                v = condb[(k - 240) * L_LEN + t0 + t];
        __nv_bfloat16 h = __float2bfloat16(v);
        xh[t * 344 + k] = h;
        xl[t * 344 + k] = __float2bfloat16(v - __bfloat162float(h));
    }

    float acc[2][8][4];
#pragma unroll
    for (int m = 0; m < 2; m++)
#pragma unroll
        for (int n = 0; n < 8; n++)
#pragma unroll
            for (int q = 0; q < 4; q++) acc[m][n][q] = 0.f;

    // GEMM1 mainloop: 4 buffers, depth-3 prefetch, ONE sync per iteration
    int kc = 0;   // c2 % 10
    for (int c2 = 0; c2 < 30; c2++) {
        CP_WAIT2();
        __syncthreads();
        if (c2 + 3 < 30) {
            const char* src = W1 + (size_t)(c2 + 3) * 20480;
            uint32_t dst = su + WQ + ((c2 + 3) & 3) * 20480;
            for (int off = tid * 16; off < 20480; off += 4096) CP_ASYNC(dst + off, src + off);
        }
        CP_COMMIT();
        const uint32_t wb = su + WQ + (c2 & 3) * 20480;
        const uint32_t xb = su + ((c2 >= 10 && c2 < 20) ? XLO : XHI);
#pragma unroll
        for (int j = 0; j < 2; j++) {
            uint32_t a[2][4], bf[4][4];
#pragma unroll
            for (int m = 0; m < 2; m++)
                ldmA(a[m], wb + ((((2 * w + m) << 4) + (lane & 15)) * 40 + ((lane >> 4) << 3) + j * 16) * 2);
            const int brow = ((lane & 16) >> 1) + (lane & 7);
            const int bcol = (kc << 5) + j * 16 + (lane & 8);
#pragma unroll
            for (int np = 0; np < 4; np++)
                ldmB(bf[np], xb + (((np << 4) + brow) * 344 + bcol) * 2);
#pragma unroll
            for (int m = 0; m < 2; m++)
#pragma unroll
                for (int nt = 0; nt < 8; nt++)
                    mma16816(acc[m][nt], a[m], &bf[nt >> 1][(nt & 1) << 1]);
        }
        if (++kc == 10) kc = 0;
    }

    // all warps done reading W1 buffers before overwriting WQ with W2
    CP_WAIT0();
    __syncthreads();

    // GEMM2 prologue: prefetch chunks 0,1 into 30720-sized bufs 0,1
    for (int c = 0; c < 2; c++) {
        for (int off = tid * 16; off < 30720; off += 4096)
            CP_ASYNC(su + WQ + c * 30720 + off, W2 + (size_t)c * 30720 + off);
        CP_COMMIT();
    }

    // activation -> z (bf16 hi/lo) [64t][136ch]  (overlaps with W2 prefetch)
    const float* bg = g_bg + blk * 240;
    __nv_bfloat16* zh = (__nv_bfloat16*)(smb + ZHI);
    __nv_bfloat16* zl = (__nv_bfloat16*)(smb + ZLO);
#pragma unroll
    for (int j = 0; j < 2; j++) {
        int ch = ((2 * w + j) << 3) + (lane >> 2);
        bool valid = ch < 120;
        float bf_ = valid ? bg[ch] : 0.f;
        float bg_ = valid ? bg[120 + ch] : 0.f;
#pragma unroll
        for (int nt = 0; nt < 8; nt++) {
            int tt = (nt << 3) + ((lane & 3) << 1);
#pragma unroll
            for (int q = 0; q < 2; q++) {
                float z = 0.f;
                if (valid) {
                    float f = acc[j][nt][q] + bf_;
                    float g = acc[j][nt][2 + q] + bg_;
                    z = tanhf_acc(f) * sigmoidf_(g);
                }
                __nv_bfloat16 h = __float2bfloat16(z);
                zh[(tt + q) * 136 + ch] = h;
                zl[(tt + q) * 136 + ch] = __float2bfloat16(z - __bfloat162float(h));
            }
        }
    }

    float ac2[3][8][4];
#pragma unroll
    for (int m = 0; m < 3; m++)
#pragma unroll
        for (int n = 0; n < 8; n++)
#pragma unroll
            for (int q = 0; q < 4; q++) ac2[m][n][q] = 0.f;

    // GEMM2 mainloop: 3 buffers, depth-2 prefetch, ONE sync per iteration
    for (int c2 = 0; c2 < 12; c2++) {
        CP_WAIT1();
        __syncthreads();                    // iter0: also publishes z
        if (c2 + 2 < 12) {
            const char* src = W2 + (size_t)(c2 + 2) * 30720;
            uint32_t dst = su + WQ + ((c2 + 2) % 3) * 30720;
            for (int off = tid * 16; off < 30720; off += 4096) CP_ASYNC(dst + off, src + off);
        }
        CP_COMMIT();
        const uint32_t wb = su + WQ + (c2 % 3) * 30720;
        const uint32_t zb = su + (((c2 >> 2) == 1) ? ZLO : ZHI);
#pragma unroll
        for (int j = 0; j < 2; j++) {
            uint32_t a[3][4], bf[4][4];
#pragma unroll
            for (int m = 0; m < 3; m++)
                ldmA(a[m], wb + ((((3 * w + m) << 4) + (lane & 15)) * 40 + ((lane >> 4) << 3) + j * 16) * 2);
            const int brow = ((lane & 16) >> 1) + (lane & 7);
            const int bcol = ((c2 & 3) << 5) + j * 16 + (lane & 8);
#pragma unroll
            for (int np = 0; np < 4; np++)
                ldmB(bf[np], zb + (((np << 4) + brow) * 136 + bcol) * 2);
#pragma unroll
            for (int m = 0; m < 3; m++)
#pragma unroll
                for (int nt = 0; nt < 8; nt++)
                    mma16816(ac2[m][nt], a[m], &bf[nt >> 1][(nt & 1) << 1]);
        }
    }

    const float* bsk = bsk_all + blk * 240;
    const float* brs = brs_all + blk * 120;
    float* skipb = g_skip + (size_t)b * 240 * L_LEN;
#pragma unroll
    for (int j = 0; j < 3; j++) {
        int mt = 3 * w + j;
#pragma unroll
        for (int h2 = 0; h2 < 2; h2++) {
            int row = (mt << 4) + (lane >> 2) + (h2 << 3);
#pragma unroll
            for (int nt = 0; nt < 8; nt++) {
                int tt = t0 + (nt << 3) + ((lane & 3) << 1);
                float v0 = ac2[j][nt][h2 << 1], v1 = ac2[j][nt][(h2 << 1) + 1];
                if (row < 240) {
                    size_t o = (size_t)row * L_LEN + tt;
                    float bb = bsk[row];
                    if (first) { skipb[o] = v0 + bb; skipb[o + 1] = v1 + bb; }
                    else       { skipb[o] += v0 + bb; skipb[o + 1] += v1 + bb; }
                } else if (row >= 256 && row < 376) {
                    int rc = row - 256;
                    size_t o = (size_t)rc * L_LEN + tt;
                    float bb = brs[rc];
                    res_out[o]     = res_in[o]     + v0 + bb;
                    res_out[o + 1] = res_in[o + 1] + v1 + bb;
                }
            }
        }
    }
}

// ---------------- head GEMM (mma.sync, deep pipeline) ----------------
#define HXHI 0
#define HXLO 33792
#define HWQ  67584
#define SMEM_HEAD 149504   // HWQ + 4*20480

__global__ void __launch_bounds__(256, 1) head_kernel(const float* __restrict__ bias,
                                                      float* __restrict__ outp, int which)
{
    char* smb = dynsmem;
    const uint32_t su = smem_u32(smb);
    const int tid = threadIdx.x, w = tid >> 5, lane = tid & 31;
    const int b = blockIdx.y, t0 = blockIdx.x << 6;

    const int Kreal = which ? 256 : 240;
    const float* srcb = (which ? g_h : g_skip) + (size_t)b * Kreal * L_LEN;
    const char* W = (const char*)(which ? g_WH2 : g_WH1);
    float* out = (which ? outp : g_h) + (size_t)b * 256 * L_LEN;

    for (int c = 0; c < 3; c++) {
        for (int off = tid * 16; off < 20480; off += 4096)
            CP_ASYNC(su + HWQ + c * 20480 + off, W + (size_t)c * 20480 + off);
        CP_COMMIT();
    }

    __nv_bfloat16* xh = (__nv_bfloat16*)(smb + HXHI);
    __nv_bfloat16* xl = (__nv_bfloat16*)(smb + HXLO);
    for (int idx = tid; idx < 256 * 64; idx += 256) {
        int t = idx & 63, k = idx >> 6;
        float v = (k < Kreal) ? srcb[k * L_LEN + t0 + t] : 0.f;
        v = v > 0.f ? v : 0.f;
        __nv_bfloat16 h = __float2bfloat16(v);
        xh[t * 264 + k] = h;
        xl[t * 264 + k] = __float2bfloat16(v - __bfloat162float(h));
    }

    float acc[2][8][4];
#pragma unroll
    for (int m = 0; m < 2; m++)
#pragma unroll
        for (int n = 0; n < 8; n++)
#pragma unroll
            for (int q = 0; q < 4; q++) acc[m][n][q] = 0.f;

    for (int c2 = 0; c2 < 24; c2++) {
        CP_WAIT2();
        __syncthreads();
        if (c2 + 3 < 24) {
            const char* src = W + (size_t)(c2 + 3) * 20480;
            uint32_t dst = su + HWQ + ((c2 + 3) & 3) * 20480;
            for (int off = tid * 16; off < 20480; off += 4096) CP_ASYNC(dst + off, src + off);
        }
        CP_COMMIT();
        const uint32_t wb = su + HWQ + (c2 & 3) * 20480;
        const uint32_t xb = su + ((c2 >= 8 && c2 < 16) ? HXLO : HXHI);
#pragma unroll
        for (int j = 0; j < 2; j++) {
            uint32_t a[2][4], bf[4][4];
#pragma unroll
            for (int m = 0; m < 2; m++)
                ldmA(a[m], wb + ((((2 * w + m) << 4) + (lane & 15)) * 40 + ((lane >> 4) << 3) + j * 16) * 2);
            const int brow = ((lane & 16) >> 1) + (lane & 7);
            const int bcol = ((c2 & 7) << 5) + j * 16 + (lane & 8);
#pragma unroll
            for (int np = 0; np < 4; np++)
                ldmB(bf[np], xb + (((np << 4) + brow) * 264 + bcol) * 2);
#pragma unroll
            for (int m = 0; m < 2; m++)
#pragma unroll
                for (int nt = 0; nt < 8; nt++)
                    mma16816(acc[m][nt], a[m], &bf[nt >> 1][(nt & 1) << 1]);
        }
    }

#pragma unroll
    for (int j = 0; j < 2; j++) {
#pragma unroll
        for (int h2 = 0; h2 < 2; h2++) {
            int ch = ((2 * w + j) << 4) + (lane >> 2) + (h2 << 3);
            float bb = bias[ch];
#pragma unroll
            for (int nt = 0; nt < 8; nt++) {
                int tt = t0 + (nt << 3) + ((lane & 3) << 1);
                size_t o = (size_t)ch * L_LEN + tt;
                out[o]     = acc[j][nt][h2 << 1] + bb;
                out[o + 1] = acc[j][nt][(h2 << 1) + 1] + bb;
            }
        }
    }
}

// ---------------- launcher ----------------
extern "C" void kernel_launch(void* const* d_in, const int* in_sizes, int n_in,
                              void* d_out, int out_size)
{
    const float* wav    = (const float*)d_in[0];
    const float* mel    = (const float*)d_in[1];
    const float* w_up   = (const float*)d_in[2];
    const float* b_up   = (const float*)d_in[3];
    const float* w_in   = (const float*)d_in[4];
    const float* b_in   = (const float*)d_in[5];
    const float* w_gate = (const float*)d_in[6];
    const float* b_gate = (const float*)d_in[7];
    const float* w_cond = (const float*)d_in[8];
    const float* b_cond = (const float*)d_in[9];
    const float* w_res  = (const float*)d_in[10];
    const float* b_res  = (const float*)d_in[11];
    const float* w_skip = (const float*)d_in[12];
    const float* b_skip = (const float*)d_in[13];
    const float* w_h1   = (const float*)d_in[14];
    const float* b_h1   = (const float*)d_in[15];
    const float* w_h2   = (const float*)d_in[16];
    const float* b_h2   = (const float*)d_in[17];
    float* out = (float*)d_out;

    const int SMEM_UP = (4 * 80 * 68 + 4 * 80 * 80) * 4;
    cudaFuncSetAttribute(block_kernel,    cudaFuncAttributeMaxDynamicSharedMemorySize, SMEM_BLOCK);
    cudaFuncSetAttribute(head_kernel,     cudaFuncAttributeMaxDynamicSharedMemorySize, SMEM_HEAD);
    cudaFuncSetAttribute(upsample_kernel, cudaFuncAttributeMaxDynamicSharedMemorySize, SMEM_UP);

    prep_kernel<<<4096, 256>>>(w_gate, b_gate, w_cond, b_cond, w_res, w_skip, w_h1, w_h2);
    upsample_kernel<<<256, 256, SMEM_UP>>>(mel, w_up, b_up);
    init_kernel<<<4096, 256>>>(wav, w_in, b_in);

    dim3 grid(NT64, 4);
    for (int i = 0; i < 16; i++)
        block_kernel<<<grid, 256, SMEM_BLOCK>>>(b_skip, b_res, i, 1 << (i & 7),
                                                (i == 0) ? 1 : 0, i & 1);

    head_kernel<<<grid, 256, SMEM_HEAD>>>(b_h1, out, 0);
    head_kernel<<<grid, 256, SMEM_HEAD>>>(b_h2, out, 1);
}

// round 8
// speedup vs baseline: 1.4157x; 1.3961x over previous
#include <cuda_runtime.h>
#include <cuda_bf16.h>
#include <math.h>
#include <stdint.h>

#define L_LEN 15872
#define NT64 248

// ---------------- device scratch ----------------
__device__ float g_cond[4 * 80 * L_LEN];
__device__ float g_res0[4 * 120 * L_LEN];
__device__ float g_res1[4 * 120 * L_LEN];
__device__ float g_skip[4 * 240 * L_LEN];
__device__ float g_h[4 * 256 * L_LEN];
__device__ float g_bg[16 * 240];

// extended-K bf16 weights (3-term hi/lo baked into K):
__device__ __align__(1024) __nv_bfloat16 g_W1[16 * 30 * 256 * 40];
__device__ __align__(1024) __nv_bfloat16 g_W2[16 * 12 * 384 * 40];
__device__ __align__(1024) __nv_bfloat16 g_WH1[24 * 256 * 40];
__device__ __align__(1024) __nv_bfloat16 g_WH2[24 * 256 * 40];

// ---------------- helpers ----------------
__device__ __forceinline__ uint32_t smem_u32(const void* p) {
    uint32_t a;
    asm("{ .reg .u64 t; cvta.to.shared.u64 t, %1; cvt.u32.u64 %0, t; }" : "=r"(a) : "l"(p));
    return a;
}
__device__ __forceinline__ void ldmA(uint32_t* a, uint32_t addr) {
    asm volatile("ldmatrix.sync.aligned.m8n8.x4.shared.b16 {%0,%1,%2,%3}, [%4];"
        : "=r"(a[0]), "=r"(a[1]), "=r"(a[2]), "=r"(a[3]) : "r"(addr));
}
__device__ __forceinline__ void ldmB(uint32_t* b, uint32_t addr) {
    asm volatile("ldmatrix.sync.aligned.m8n8.x4.shared.b16 {%0,%1,%2,%3}, [%4];"
        : "=r"(b[0]), "=r"(b[1]), "=r"(b[2]), "=r"(b[3]) : "r"(addr));
}
__device__ __forceinline__ void mma16816(float* c, const uint32_t* a, const uint32_t* b) {
    asm volatile("mma.sync.aligned.m16n8k16.row.col.f32.bf16.bf16.f32 "
        "{%0,%1,%2,%3}, {%4,%5,%6,%7}, {%8,%9}, {%0,%1,%2,%3};"
        : "+f"(c[0]), "+f"(c[1]), "+f"(c[2]), "+f"(c[3])
        : "r"(a[0]), "r"(a[1]), "r"(a[2]), "r"(a[3]), "r"(b[0]), "r"(b[1]));
}
#define CP_ASYNC(dst, src) asm volatile("cp.async.ca.shared.global [%0], [%1], 16;" :: "r"(dst), "l"(src))
#define CP_COMMIT()        asm volatile("cp.async.commit_group;" ::: "memory")
#define CP_WAIT2()         asm volatile("cp.async.wait_group 2;" ::: "memory")
#define CP_WAIT1()         asm volatile("cp.async.wait_group 1;" ::: "memory")
#define CP_WAIT0()         asm volatile("cp.async.wait_group 0;" ::: "memory")

__device__ __forceinline__ __nv_bfloat16 bsel(float v, int term) {
    __nv_bfloat16 h = __float2bfloat16(v);
    if (term < 2) return h;
    return __float2bfloat16(v - __bfloat162float(h));
}
__device__ __forceinline__ float sigmoidf_(float g) {
    return __fdividef(1.f, 1.f + __expf(-g));
}
__device__ __forceinline__ float tanhf_acc(float f) {
    f = fminf(15.f, fmaxf(-15.f, f));
    float e = expm1f(2.f * f);
    return __fdividef(e, e + 2.f);
}

// ---------------- weight prep ----------------
__global__ void prep_kernel(const float* __restrict__ w_gate, const float* __restrict__ b_gate,
                            const float* __restrict__ w_cond, const float* __restrict__ b_cond,
                            const float* __restrict__ w_res,  const float* __restrict__ w_skip,
                            const float* __restrict__ w_h1,   const float* __restrict__ w_h2)
{
    const int NW1 = 16 * 30 * 256 * 40;
    const int NW2 = 16 * 12 * 384 * 40;
    const int NH  = 24 * 256 * 40;
    const int total = NW1 + NW2 + 2 * NH + 16 * 240;
    for (int idx = blockIdx.x * blockDim.x + threadIdx.x; idx < total;
         idx += gridDim.x * blockDim.x) {
        int i = idx;
        if (i < NW1) {
            int blk = i / 307200, r = i % 307200;
            int c2 = r / 10240, r2 = r % 10240;
            int row = r2 / 40, col = r2 % 40;
            int term = c2 / 10;
            int k = (c2 % 10) * 32 + col;
            int T = row >> 4, rr = row & 15;
            int chf = (T << 3) + (rr & 7);
            float v = 0.f;
            if (col < 32 && chf < 120) {
                int gch = (rr < 8) ? chf : (120 + chf);
                if (k < 120)       v = w_gate[((blk * 240 + gch) * 120 + k) * 2];
                else if (k < 240)  v = w_gate[((blk * 240 + gch) * 120 + (k - 120)) * 2 + 1];
                else               v = w_cond[(blk * 240 + gch) * 80 + (k - 240)];
            }
            g_W1[i] = bsel(v, term);
        } else if ((i -= NW1) < NW2) {
            int blk = i / 184320, r = i % 184320;
            int c2 = r / 15360, r2 = r % 15360;
            int row = r2 / 40, col = r2 % 40;
            int term = c2 / 4;
            int k = (c2 % 4) * 32 + col;
            float v = 0.f;
            if (col < 32 && k < 120) {
                if (row < 240)                    v = w_skip[(blk * 240 + row) * 120 + k];
                else if (row >= 256 && row < 376) v = w_res[(blk * 120 + (row - 256)) * 120 + k];
            }
            g_W2[i] = bsel(v, term);
        } else if ((i -= NW2) < NH) {
            int c2 = i / 10240, r2 = i % 10240;
            int row = r2 / 40, col = r2 % 40;
            int term = c2 / 8;
            int k = (c2 % 8) * 32 + col;
            float v = (col < 32 && k < 240) ? w_h1[row * 240 + k] : 0.f;
            g_WH1[i] = bsel(v, term);
        } else if ((i -= NH) < NH) {
            int c2 = i / 10240, r2 = i % 10240;
            int row = r2 / 40, col = r2 % 40;
            int term = c2 / 8;
            int k = (c2 % 8) * 32 + col;
            float v = (col < 32) ? w_h2[row * 256 + k] : 0.f;
            g_WH2[i] = bsel(v, term);
        } else {
            i -= NH;
            g_bg[i] = b_gate[i] + b_cond[i];
        }
    }
}

// ---------------- residual init ----------------
__global__ void init_kernel(const float* __restrict__ wav, const float* __restrict__ w_in,
                            const float* __restrict__ b_in)
{
    const int total = 4 * 120 * L_LEN;
    for (int idx = blockIdx.x * blockDim.x + threadIdx.x; idx < total;
         idx += gridDim.x * blockDim.x) {
        int t = idx % L_LEN;
        int br = idx / L_LEN;
        int r = br % 120, b = br / 120;
        g_res0[idx] = w_in[r] * wav[b * L_LEN + t] + b_in[r];
    }
}

// ---------------- mel upsample (fp32) ----------------
extern __shared__ char dynsmem[];

__global__ void __launch_bounds__(256) upsample_kernel(const float* __restrict__ mel,
                                                       const float* __restrict__ w_up,
                                                       const float* __restrict__ b_up)
{
    float* mel_s = (float*)dynsmem;
    float* ws    = (float*)dynsmem + 4 * 80 * 68;
    const int p = blockIdx.x, tid = threadIdx.x;

    for (int idx = tid; idx < 4 * 80 * 68; idx += 256) mel_s[idx] = 0.f;
    __syncthreads();
    for (int idx = tid; idx < 4 * 80 * 63; idx += 256)
        mel_s[(idx / 63) * 68 + (idx % 63) + 1] = mel[idx];
    bool valid[4];
#pragma unroll
    for (int v = 0; v < 4; v++) {
        int kk = 400 + p + 256 * (v - 2);
        valid[v] = (kk >= 0) && (kk < 800);
        if (valid[v])
            for (int idx = tid; idx < 6400; idx += 256)
                ws[(v * 80 + idx / 80) * 80 + idx % 80] = w_up[((idx / 80) * 80 + idx % 80) * 800 + kk];
    }
    __syncthreads();

    for (int tile = tid; tile < 320; tile += 256) {
        int og = tile >> 5, b = (tile >> 3) & 3, ug = tile & 7;
        int o0 = og * 8, u0 = ug * 8;
        float acc[8][8];
#pragma unroll
        for (int a = 0; a < 8; a++)
#pragma unroll
            for (int c = 0; c < 8; c++) acc[a][c] = 0.f;
        const float* msb = mel_s + b * 80 * 68;
#pragma unroll
        for (int v = 0; v < 4; v++) {
            if (!valid[v]) continue;
            int vv = v - 2;
#pragma unroll 4
            for (int m = 0; m < 80; m++) {
                const float* wr = ws + (v * 80 + m) * 80 + o0;
                float4 wA = *(const float4*)wr;
                float4 wB = *(const float4*)(wr + 4);
                float wv[8] = {wA.x, wA.y, wA.z, wA.w, wB.x, wB.y, wB.z, wB.w};
                const float* xr = msb + m * 68 + (u0 - vv) + 1;
                float xv[8];
#pragma unroll
                for (int c = 0; c < 8; c++) xv[c] = xr[c];
#pragma unroll
                for (int a = 0; a < 8; a++)
#pragma unroll
                    for (int c = 0; c < 8; c++)
                        acc[a][c] = fmaf(wv[a], xv[c], acc[a][c]);
            }
        }
#pragma unroll
        for (int a = 0; a < 8; a++) {
            float bo = b_up[o0 + a];
#pragma unroll
            for (int c = 0; c < 8; c++)
                if (u0 + c < 62)
                    g_cond[((size_t)b * 80 + o0 + a) * L_LEN + 256 * (u0 + c) + p] = acc[a][c] + bo;
        }
    }
}

// ---------------- fused residual block (mma.sync, 512 threads / 16 warps) ----------------
#define XHI 0
#define XLO 44032
#define ZHI 88064
#define ZLO 105472
#define WQ  122880
#define SMEM_BLOCK 215040

__global__ void __launch_bounds__(512, 1) block_kernel(const float* __restrict__ bsk_all,
                                                       const float* __restrict__ brs_all,
                                                       int blk, int d, int first, int parity)
{
    char* smb = dynsmem;
    const uint32_t su = smem_u32(smb);
    const int tid = threadIdx.x, w = tid >> 5, lane = tid & 31;
    const int wr = w >> 1, wt = w & 1;          // row-group 0..7, t-half 0..1
    const int b = blockIdx.y, t0 = blockIdx.x << 6;

    const float* res_in  = (parity ? g_res1 : g_res0) + (size_t)b * 120 * L_LEN;
    float*       res_out = (parity ? g_res0 : g_res1) + (size_t)b * 120 * L_LEN;
    const float* condb   = g_cond + (size_t)b * 80 * L_LEN;

    const char* W1 = (const char*)(g_W1 + (size_t)blk * 30 * 256 * 40);
    const char* W2 = (const char*)(g_W2 + (size_t)blk * 12 * 384 * 40);

    // GEMM1 prologue: prefetch chunks 0..2 into bufs 0..2
    for (int c = 0; c < 3; c++) {
        for (int off = tid * 16; off < 20480; off += 8192)
            CP_ASYNC(su + WQ + c * 20480 + off, W1 + (size_t)c * 20480 + off);
        CP_COMMIT();
    }

    // stage X: [64t][320k] fp32 -> bf16 hi/lo
    __nv_bfloat16* xh = (__nv_bfloat16*)(smb + XHI);
    __nv_bfloat16* xl = (__nv_bfloat16*)(smb + XLO);
    for (int idx = tid; idx < 320 * 64; idx += 512) {
        int t = idx & 63, k = idx >> 6;
        float v;
        if (k < 120)      { int ts = t0 + t - d; v = (ts >= 0) ? res_in[k * L_LEN + ts] : 0.f; }
        else if (k < 240)   v = res_in[(k - 120) * L_LEN + t0 + t];
        else                v = condb[(k - 240) * L_LEN + t0 + t];
        __nv_bfloat16 h = __float2bfloat16(v);
        xh[t * 344 + k] = h;
        xl[t * 344 + k] = __float2bfloat16(v - __bfloat162float(h));
    }

    float acc[2][4][4];
#pragma unroll
    for (int m = 0; m < 2; m++)
#pragma unroll
        for (int n = 0; n < 4; n++)
#pragma unroll
            for (int q = 0; q < 4; q++) acc[m][n][q] = 0.f;

    const int brow = ((lane & 16) >> 1) + (lane & 7);

    // GEMM1 mainloop
    int kc = 0;
    for (int c2 = 0; c2 < 30; c2++) {
        CP_WAIT2();
        __syncthreads();
        if (c2 + 3 < 30) {
            const char* src = W1 + (size_t)(c2 + 3) * 20480;
            uint32_t dst = su + WQ + ((c2 + 3) & 3) * 20480;
            for (int off = tid * 16; off < 20480; off += 8192) CP_ASYNC(dst + off, src + off);
        }
        CP_COMMIT();
        const uint32_t wb = su + WQ + (c2 & 3) * 20480;
        const uint32_t xb = su + ((c2 >= 10 && c2 < 20) ? XLO : XHI);
#pragma unroll
        for (int j = 0; j < 2; j++) {
            uint32_t a[2][4], bf[2][4];
#pragma unroll
            for (int m = 0; m < 2; m++) {
                int mt = 2 * wr + m;
                ldmA(a[m], wb + (((mt << 4) + (lane & 15)) * 40 + ((lane >> 4) << 3) + j * 16) * 2);
            }
            const int bcol = (kc << 5) + j * 16 + (lane & 8);
#pragma unroll
            for (int np = 0; np < 2; np++)
                ldmB(bf[np], xb + (((wt << 5) + (np << 4) + brow) * 344 + bcol) * 2);
#pragma unroll
            for (int m = 0; m < 2; m++)
#pragma unroll
                for (int nt = 0; nt < 4; nt++)
                    mma16816(acc[m][nt], a[m], &bf[nt >> 1][(nt & 1) << 1]);
        }
        if (++kc == 10) kc = 0;
    }

    CP_WAIT0();
    __syncthreads();

    // GEMM2 prologue
    for (int c = 0; c < 2; c++) {
        for (int off = tid * 16; off < 30720; off += 8192)
            CP_ASYNC(su + WQ + c * 30720 + off, W2 + (size_t)c * 30720 + off);
        CP_COMMIT();
    }

    // activation -> z (bf16 hi/lo) [64t][136ch]
    const float* bg = g_bg + blk * 240;
    __nv_bfloat16* zh = (__nv_bfloat16*)(smb + ZHI);
    __nv_bfloat16* zl = (__nv_bfloat16*)(smb + ZLO);
#pragma unroll
    for (int m = 0; m < 2; m++) {
        int mt = 2 * wr + m;
        int ch = (mt << 3) + (lane >> 2);
        bool valid = ch < 120;
        float bf_ = valid ? bg[ch] : 0.f;
        float bg_ = valid ? bg[120 + ch] : 0.f;
#pragma unroll
        for (int nt = 0; nt < 4; nt++) {
            int tt = (wt << 5) + (nt << 3) + ((lane & 3) << 1);
#pragma unroll
            for (int q = 0; q < 2; q++) {
                float z = 0.f;
                if (valid) {
                    float f = acc[m][nt][q] + bf_;
                    float g = acc[m][nt][2 + q] + bg_;
                    z = tanhf_acc(f) * sigmoidf_(g);
                }
                __nv_bfloat16 h = __float2bfloat16(z);
                zh[(tt + q) * 136 + ch] = h;
                zl[(tt + q) * 136 + ch] = __float2bfloat16(z - __bfloat162float(h));
            }
        }
    }

    float ac2[3][4][4];
#pragma unroll
    for (int m = 0; m < 3; m++)
#pragma unroll
        for (int n = 0; n < 4; n++)
#pragma unroll
            for (int q = 0; q < 4; q++) ac2[m][n][q] = 0.f;

    // GEMM2 mainloop
    for (int c2 = 0; c2 < 12; c2++) {
        CP_WAIT1();
        __syncthreads();                    // iter0 also publishes z
        if (c2 + 2 < 12) {
            const char* src = W2 + (size_t)(c2 + 2) * 30720;
            uint32_t dst = su + WQ + ((c2 + 2) % 3) * 30720;
            for (int off = tid * 16; off < 30720; off += 8192) CP_ASYNC(dst + off, src + off);
        }
        CP_COMMIT();
        const uint32_t wb = su + WQ + (c2 % 3) * 30720;
        const uint32_t zb = su + (((c2 >> 2) == 1) ? ZLO : ZHI);
#pragma unroll
        for (int j = 0; j < 2; j++) {
            uint32_t a[3][4], bf[2][4];
#pragma unroll
            for (int m = 0; m < 3; m++) {
                int mt = 3 * wr + m;
                ldmA(a[m], wb + (((mt << 4) + (lane & 15)) * 40 + ((lane >> 4) << 3) + j * 16) * 2);
            }
            const int bcol = ((c2 & 3) << 5) + j * 16 + (lane & 8);
#pragma unroll
            for (int np = 0; np < 2; np++)
                ldmB(bf[np], zb + (((wt << 5) + (np << 4) + brow) * 136 + bcol) * 2);
#pragma unroll
            for (int m = 0; m < 3; m++)
#pragma unroll
                for (int nt = 0; nt < 4; nt++)
                    mma16816(ac2[m][nt], a[m], &bf[nt >> 1][(nt & 1) << 1]);
        }
    }

    const float* bsk = bsk_all + blk * 240;
    const float* brs = brs_all + blk * 120;
    float* skipb = g_skip + (size_t)b * 240 * L_LEN;
#pragma unroll
    for (int m = 0; m < 3; m++) {
        int mt = 3 * wr + m;
#pragma unroll
        for (int h2 = 0; h2 < 2; h2++) {
            int row = (mt << 4) + (lane >> 2) + (h2 << 3);
#pragma unroll
            for (int nt = 0; nt < 4; nt++) {
                int tt = t0 + (wt << 5) + (nt << 3) + ((lane & 3) << 1);
                float v0 = ac2[m][nt][h2 << 1], v1 = ac2[m][nt][(h2 << 1) + 1];
                if (row < 240) {
                    size_t o = (size_t)row * L_LEN + tt;
                    float bb = bsk[row];
                    if (first) { skipb[o] = v0 + bb; skipb[o + 1] = v1 + bb; }
                    else       { skipb[o] += v0 + bb; skipb[o + 1] += v1 + bb; }
                } else if (row >= 256 && row < 376) {
                    int rc = row - 256;
                    size_t o = (size_t)rc * L_LEN + tt;
                    float bb = brs[rc];
                    res_out[o]     = res_in[o]     + v0 + bb;
                    res_out[o + 1] = res_in[o + 1] + v1 + bb;
                }
            }
        }
    }
}

// ---------------- head GEMM (mma.sync, 512 threads) ----------------
#define HXHI 0
#define HXLO 33792
#define HWQ  67584
#define SMEM_HEAD 149504

__global__ void __launch_bounds__(512, 1) head_kernel(const float* __restrict__ bias,
                                                      float* __restrict__ outp, int which)
{
    char* smb = dynsmem;
    const uint32_t su = smem_u32(smb);
    const int tid = threadIdx.x, w = tid >> 5, lane = tid & 31;
    const int wr = w >> 1, wt = w & 1;
    const int b = blockIdx.y, t0 = blockIdx.x << 6;

    const int Kreal = which ? 256 : 240;
    const float* srcb = (which ? g_h : g_skip) + (size_t)b * Kreal * L_LEN;
    const char* W = (const char*)(which ? g_WH2 : g_WH1);
    float* out = (which ? outp : g_h) + (size_t)b * 256 * L_LEN;

    for (int c = 0; c < 3; c++) {
        for (int off = tid * 16; off < 20480; off += 8192)
            CP_ASYNC(su + HWQ + c * 20480 + off, W + (size_t)c * 20480 + off);
        CP_COMMIT();
    }

    __nv_bfloat16* xh = (__nv_bfloat16*)(smb + HXHI);
    __nv_bfloat16* xl = (__nv_bfloat16*)(smb + HXLO);
    for (int idx = tid; idx < 256 * 64; idx += 512) {
        int t = idx & 63, k = idx >> 6;
        float v = (k < Kreal) ? srcb[k * L_LEN + t0 + t] : 0.f;
        v = v > 0.f ? v : 0.f;
        __nv_bfloat16 h = __float2bfloat16(v);
        xh[t * 264 + k] = h;
        xl[t * 264 + k] = __float2bfloat16(v - __bfloat162float(h));
    }

    float acc[2][4][4];
#pragma unroll
    for (int m = 0; m < 2; m++)
#pragma unroll
        for (int n = 0; n < 4; n++)
#pragma unroll
            for (int q = 0; q < 4; q++) acc[m][n][q] = 0.f;

    const int brow = ((lane & 16) >> 1) + (lane & 7);

    for (int c2 = 0; c2 < 24; c2++) {
        CP_WAIT2();
        __syncthreads();
        if (c2 + 3 < 24) {
            const char* src = W + (size_t)(c2 + 3) * 20480;
            uint32_t dst = su + HWQ + ((c2 + 3) & 3) * 20480;
            for (int off = tid * 16; off < 20480; off += 8192) CP_ASYNC(dst + off, src + off);
        }
        CP_COMMIT();
        const uint32_t wb = su + HWQ + (c2 & 3) * 20480;
        const uint32_t xb = su + ((c2 >= 8 && c2 < 16) ? HXLO : HXHI);
#pragma unroll
        for (int j = 0; j < 2; j++) {
            uint32_t a[2][4], bf[2][4];
#pragma unroll
            for (int m = 0; m < 2; m++) {
                int mt = 2 * wr + m;
                ldmA(a[m], wb + (((mt << 4) + (lane & 15)) * 40 + ((lane >> 4) << 3) + j * 16) * 2);
            }
            const int bcol = ((c2 & 7) << 5) + j * 16 + (lane & 8);
#pragma unroll
            for (int np = 0; np < 2; np++)
                ldmB(bf[np], xb + (((wt << 5) + (np << 4) + brow) * 264 + bcol) * 2);
#pragma unroll
            for (int m = 0; m < 2; m++)
#pragma unroll
                for (int nt = 0; nt < 4; nt++)
                    mma16816(acc[m][nt], a[m], &bf[nt >> 1][(nt & 1) << 1]);
        }
    }

#pragma unroll
    for (int m = 0; m < 2; m++) {
        int mt = 2 * wr + m;
#pragma unroll
        for (int h2 = 0; h2 < 2; h2++) {
            int ch = (mt << 4) + (lane >> 2) + (h2 << 3);
            float bb = bias[ch];
#pragma unroll
            for (int nt = 0; nt < 4; nt++) {
                int tt = t0 + (wt << 5) + (nt << 3) + ((lane & 3) << 1);
                size_t o = (size_t)ch * L_LEN + tt;
                out[o]     = acc[m][nt][h2 << 1] + bb;
                out[o + 1] = acc[m][nt][(h2 << 1) + 1] + bb;
            }
        }
    }
}

// ---------------- launcher ----------------
extern "C" void kernel_launch(void* const* d_in, const int* in_sizes, int n_in,
                              void* d_out, int out_size)
{
    const float* wav    = (const float*)d_in[0];
    const float* mel    = (const float*)d_in[1];
    const float* w_up   = (const float*)d_in[2];
    const float* b_up   = (const float*)d_in[3];
    const float* w_in   = (const float*)d_in[4];
    const float* b_in   = (const float*)d_in[5];
    const float* w_gate = (const float*)d_in[6];
    const float* b_gate = (const float*)d_in[7];
    const float* w_cond = (const float*)d_in[8];
    const float* b_cond = (const float*)d_in[9];
    const float* w_res  = (const float*)d_in[10];
    const float* b_res  = (const float*)d_in[11];
    const float* w_skip = (const float*)d_in[12];
    const float* b_skip = (const float*)d_in[13];
    const float* w_h1   = (const float*)d_in[14];
    const float* b_h1   = (const float*)d_in[15];
    const float* w_h2   = (const float*)d_in[16];
    const float* b_h2   = (const float*)d_in[17];
    float* out = (float*)d_out;

    const int SMEM_UP = (4 * 80 * 68 + 4 * 80 * 80) * 4;
    cudaFuncSetAttribute(block_kernel,    cudaFuncAttributeMaxDynamicSharedMemorySize, SMEM_BLOCK);
    cudaFuncSetAttribute(head_kernel,     cudaFuncAttributeMaxDynamicSharedMemorySize, SMEM_HEAD);
    cudaFuncSetAttribute(upsample_kernel, cudaFuncAttributeMaxDynamicSharedMemorySize, SMEM_UP);

    prep_kernel<<<4096, 256>>>(w_gate, b_gate, w_cond, b_cond, w_res, w_skip, w_h1, w_h2);
    upsample_kernel<<<256, 256, SMEM_UP>>>(mel, w_up, b_up);
    init_kernel<<<4096, 256>>>(wav, w_in, b_in);

    dim3 grid(NT64, 4);
    for (int i = 0; i < 16; i++)
        block_kernel<<<grid, 512, SMEM_BLOCK>>>(b_skip, b_res, i, 1 << (i & 7),
                                                (i == 0) ? 1 : 0, i & 1);

    head_kernel<<<grid, 512, SMEM_HEAD>>>(b_h1, out, 0);
    head_kernel<<<grid, 512, SMEM_HEAD>>>(b_h2, out, 1);
}

// round 11
// speedup vs baseline: 1.7499x; 1.2360x over previous
#include <cuda_runtime.h>
#include <cuda_bf16.h>
#include <math.h>
#include <stdint.h>

#define L_LEN 15872
#define NT64 248

// ---------------- device scratch ----------------
__device__ float g_cond[4 * 80 * L_LEN];
__device__ float g_res0[4 * 120 * L_LEN];
__device__ float g_res1[4 * 120 * L_LEN];
__device__ float g_skip[4 * 240 * L_LEN];
__device__ float g_h[4 * 256 * L_LEN];
__device__ float g_bg[16 * 240];

// fragment-major bf16 weights: per fragment (c2, mtile, j) -> 32 lanes x 16B (uint4)
// reg r, lane: row = mt*16 + (r&1)*8 + lane/4 ; k = j*16 + (r&2)*4 + (lane&3)*2 + h
__device__ __align__(16) __nv_bfloat16 g_W1f[16 * 30 * 16 * 2 * 32 * 8];  // 3932160
__device__ __align__(16) __nv_bfloat16 g_W2f[16 * 12 * 24 * 2 * 32 * 8];  // 2359296
__device__ __align__(16) __nv_bfloat16 g_WH1f[24 * 16 * 2 * 32 * 8];      // 196608
__device__ __align__(16) __nv_bfloat16 g_WH2f[24 * 16 * 2 * 32 * 8];

// ---------------- helpers ----------------
__device__ __forceinline__ uint32_t smem_u32(const void* p) {
    uint32_t a;
    asm("{ .reg .u64 t; cvta.to.shared.u64 t, %1; cvt.u32.u64 %0, t; }" : "=r"(a) : "l"(p));
    return a;
}
__device__ __forceinline__ void ldmB(uint32_t* b, uint32_t addr) {
    asm volatile("ldmatrix.sync.aligned.m8n8.x4.shared.b16 {%0,%1,%2,%3}, [%4];"
        : "=r"(b[0]), "=r"(b[1]), "=r"(b[2]), "=r"(b[3]) : "r"(addr));
}
__device__ __forceinline__ void mma16816(float* c, const uint32_t* a, const uint32_t* b) {
    asm volatile("mma.sync.aligned.m16n8k16.row.col.f32.bf16.bf16.f32 "
        "{%0,%1,%2,%3}, {%4,%5,%6,%7}, {%8,%9}, {%0,%1,%2,%3};"
        : "+f"(c[0]), "+f"(c[1]), "+f"(c[2]), "+f"(c[3])
        : "r"(a[0]), "r"(a[1]), "r"(a[2]), "r"(a[3]), "r"(b[0]), "r"(b[1]));
}
__device__ __forceinline__ __nv_bfloat16 bsel(float v, int term) {
    __nv_bfloat16 h = __float2bfloat16(v);
    if (term < 2) return h;
    return __float2bfloat16(v - __bfloat162float(h));
}
__device__ __forceinline__ float sigmoidf_(float g) {
    return __fdividef(1.f, 1.f + __expf(-g));
}
__device__ __forceinline__ float tanhf_acc(float f) {
    f = fminf(15.f, fmaxf(-15.f, f));
    float e = expm1f(2.f * f);
    return __fdividef(e, e + 2.f);
}

// ---------------- weight prep (fragment-major) ----------------
__global__ void prep_kernel(const float* __restrict__ w_gate, const float* __restrict__ b_gate,
                            const float* __restrict__ w_cond, const float* __restrict__ b_cond,
                            const float* __restrict__ w_res,  const float* __restrict__ w_skip,
                            const float* __restrict__ w_h1,   const float* __restrict__ w_h2)
{
    const int NW1 = 16 * 245760;
    const int NW2 = 16 * 147456;
    const int NH  = 196608;
    const int total = NW1 + NW2 + 2 * NH + 16 * 240;
    for (int idx = blockIdx.x * blockDim.x + threadIdx.x; idx < total;
         idx += gridDim.x * blockDim.x) {
        int i = idx;
        if (i < NW1) {
            int blk = i / 245760, q = i % 245760;
            int c2 = q / 8192;  q %= 8192;
            int mt = q / 512;   q %= 512;
            int j  = q / 256;   q %= 256;
            int lane = q / 8;   int e = q % 8;
            int r4 = e >> 1, h = e & 1;
            int kk = j * 16 + (r4 & 2) * 4 + (lane & 3) * 2 + h;
            int k = (c2 % 10) * 32 + kk, term = c2 / 10;
            int chf = (mt << 3) + (lane >> 2);
            float v = 0.f;
            if (chf < 120) {
                int gch = ((r4 & 1) == 0) ? chf : 120 + chf;
                if (k < 120)       v = w_gate[((blk * 240 + gch) * 120 + k) * 2];
                else if (k < 240)  v = w_gate[((blk * 240 + gch) * 120 + (k - 120)) * 2 + 1];
                else               v = w_cond[(blk * 240 + gch) * 80 + (k - 240)];
            }
            g_W1f[i] = bsel(v, term);
        } else if ((i -= NW1) < NW2) {
            int blk = i / 147456, q = i % 147456;
            int c2 = q / 12288; q %= 12288;
            int mt = q / 512;   q %= 512;
            int j  = q / 256;   q %= 256;
            int lane = q / 8;   int e = q % 8;
            int r4 = e >> 1, h = e & 1;
            int row = mt * 16 + (r4 & 1) * 8 + (lane >> 2);
            int kk = j * 16 + (r4 & 2) * 4 + (lane & 3) * 2 + h;
            int k = (c2 % 4) * 32 + kk, term = c2 / 4;
            float v = 0.f;
            if (k < 120) {
                if (row < 240)                    v = w_skip[(blk * 240 + row) * 120 + k];
                else if (row >= 256 && row < 376) v = w_res[(blk * 120 + (row - 256)) * 120 + k];
            }
            g_W2f[i] = bsel(v, term);
        } else if ((i -= NW2) < 2 * NH) {
            int which = i / NH;
            int q = i % NH;
            int c2 = q / 8192;  q %= 8192;
            int mt = q / 512;   q %= 512;
            int j  = q / 256;   q %= 256;
            int lane = q / 8;   int e = q % 8;
            int r4 = e >> 1, h = e & 1;
            int row = mt * 16 + (r4 & 1) * 8 + (lane >> 2);
            int kk = j * 16 + (r4 & 2) * 4 + (lane & 3) * 2 + h;
            int k = (c2 % 8) * 32 + kk, term = c2 / 8;
            float v;
            if (which == 0) v = (k < 240) ? w_h1[row * 240 + k] : 0.f;
            else            v = w_h2[row * 256 + k];
            (which == 0 ? g_WH1f : g_WH2f)[i % NH] = bsel(v, term);
        } else {
            i -= 2 * NH;
            g_bg[i] = b_gate[i] + b_cond[i];
        }
    }
}

// ---------------- residual init ----------------
__global__ void init_kernel(const float* __restrict__ wav, const float* __restrict__ w_in,
                            const float* __restrict__ b_in)
{
    const int total = 4 * 120 * L_LEN;
    for (int idx = blockIdx.x * blockDim.x + threadIdx.x; idx < total;
         idx += gridDim.x * blockDim.x) {
        int t = idx % L_LEN;
        int br = idx / L_LEN;
        int r = br % 120, b = br / 120;
        g_res0[idx] = w_in[r] * wav[b * L_LEN + t] + b_in[r];
    }
}

// ---------------- mel upsample (fp32) ----------------
extern __shared__ char dynsmem[];

__global__ void __launch_bounds__(256) upsample_kernel(const float* __restrict__ mel,
                                                       const float* __restrict__ w_up,
                                                       const float* __restrict__ b_up)
{
    float* mel_s = (float*)dynsmem;
    float* ws    = (float*)dynsmem + 4 * 80 * 68;
    const int p = blockIdx.x, tid = threadIdx.x;

    for (int idx = tid; idx < 4 * 80 * 68; idx += 256) mel_s[idx] = 0.f;
    __syncthreads();
    for (int idx = tid; idx < 4 * 80 * 63; idx += 256)
        mel_s[(idx / 63) * 68 + (idx % 63) + 1] = mel[idx];
    bool valid[4];
#pragma unroll
    for (int v = 0; v < 4; v++) {
        int kk = 400 + p + 256 * (v - 2);
        valid[v] = (kk >= 0) && (kk < 800);
        if (valid[v])
            for (int idx = tid; idx < 6400; idx += 256)
                ws[(v * 80 + idx / 80) * 80 + idx % 80] = w_up[((idx / 80) * 80 + idx % 80) * 800 + kk];
    }
    __syncthreads();

    for (int tile = tid; tile < 320; tile += 256) {
        int og = tile >> 5, b = (tile >> 3) & 3, ug = tile & 7;
        int o0 = og * 8, u0 = ug * 8;
        float acc[8][8];
#pragma unroll
        for (int a = 0; a < 8; a++)
#pragma unroll
            for (int c = 0; c < 8; c++) acc[a][c] = 0.f;
        const float* msb = mel_s + b * 80 * 68;
#pragma unroll
        for (int v = 0; v < 4; v++) {
            if (!valid[v]) continue;
            int vv = v - 2;
#pragma unroll 4
            for (int m = 0; m < 80; m++) {
                const float* wr = ws + (v * 80 + m) * 80 + o0;
                float4 wA = *(const float4*)wr;
                float4 wB = *(const float4*)(wr + 4);
                float wv[8] = {wA.x, wA.y, wA.z, wA.w, wB.x, wB.y, wB.z, wB.w};
                const float* xr = msb + m * 68 + (u0 - vv) + 1;
                float xv[8];
#pragma unroll
                for (int c = 0; c < 8; c++) xv[c] = xr[c];
#pragma unroll
                for (int a = 0; a < 8; a++)
#pragma unroll
                    for (int c = 0; c < 8; c++)
                        acc[a][c] = fmaf(wv[a], xv[c], acc[a][c]);
            }
        }
#pragma unroll
        for (int a = 0; a < 8; a++) {
            float bo = b_up[o0 + a];
#pragma unroll
            for (int c = 0; c < 8; c++)
                if (u0 + c < 62)
                    g_cond[((size_t)b * 80 + o0 + a) * L_LEN + 256 * (u0 + c) + p] = acc[a][c] + bo;
        }
    }
}

// ---------------- fused residual block (mma.sync, barrier-free mainloops) ----------------
#define XHI 0
#define XLO 44032
#define ZHI 88064
#define ZLO 105472
#define SMEM_BLOCK 122880

__global__ void __launch_bounds__(512, 1) block_kernel(const float* __restrict__ bsk_all,
                                                       const float* __restrict__ brs_all,
                                                       int blk, int d, int first, int parity)
{
    char* smb = dynsmem;
    const uint32_t su = smem_u32(smb);
    const int tid = threadIdx.x, w = tid >> 5, lane = tid & 31;
    const int wr = w >> 1, wt = w & 1;
    const int b = blockIdx.y, t0 = blockIdx.x << 6;

    const float* res_in  = (parity ? g_res1 : g_res0) + (size_t)b * 120 * L_LEN;
    float*       res_out = (parity ? g_res0 : g_res1) + (size_t)b * 120 * L_LEN;
    const float* condb   = g_cond + (size_t)b * 80 * L_LEN;

    const uint4* A1 = ((const uint4*)g_W1f) + (size_t)blk * (30 * 16 * 2 * 32);
    const uint4* A2 = ((const uint4*)g_W2f) + (size_t)blk * (12 * 24 * 2 * 32);

    // stage X: [64t][320k] fp32 -> bf16 hi/lo
    __nv_bfloat16* xh = (__nv_bfloat16*)(smb + XHI);
    __nv_bfloat16* xl = (__nv_bfloat16*)(smb + XLO);
    for (int idx = tid; idx < 320 * 64; idx += 512) {
        int t = idx & 63, k = idx >> 6;
        float v;
        if (k < 120)      { int ts = t0 + t - d; v = (ts >= 0) ? res_in[k * L_LEN + ts] : 0.f; }
        else if (k < 240)   v = res_in[(k - 120) * L_LEN + t0 + t];
        else                v = condb[(k - 240) * L_LEN + t0 + t];
        __nv_bfloat16 h = __float2bfloat16(v);
        xh[t * 344 + k] = h;
        xl[t * 344 + k] = __float2bfloat16(v - __bfloat162float(h));
    }
    __syncthreads();

    float acc[2][4][4];
#pragma unroll
    for (int m = 0; m < 2; m++)
#pragma unroll
        for (int n = 0; n < 4; n++)
#pragma unroll
            for (int q = 0; q < 4; q++) acc[m][n][q] = 0.f;

    const int brow = ((lane & 16) >> 1) + (lane & 7);

    // GEMM1: register-double-buffered A fragments from L2, no barriers
    uint4 curA[2][2], nxtA[2][2];
#pragma unroll
    for (int m = 0; m < 2; m++)
#pragma unroll
        for (int j = 0; j < 2; j++)
            curA[m][j] = A1[(((0 * 16 + (2 * wr + m)) * 2) + j) * 32 + lane];

    int kc = 0;
    for (int c2 = 0; c2 < 30; c2++) {
        if (c2 < 29) {
#pragma unroll
            for (int m = 0; m < 2; m++)
#pragma unroll
                for (int j = 0; j < 2; j++)
                    nxtA[m][j] = A1[((((c2 + 1) * 16 + (2 * wr + m)) * 2) + j) * 32 + lane];
        }
        const uint32_t xb = su + ((c2 >= 10 && c2 < 20) ? XLO : XHI);
#pragma unroll
        for (int j = 0; j < 2; j++) {
            uint32_t bf[2][4];
            const int bcol = (kc << 5) + j * 16 + (lane & 8);
#pragma unroll
            for (int np = 0; np < 2; np++)
                ldmB(bf[np], xb + (((wt << 5) + (np << 4) + brow) * 344 + bcol) * 2);
#pragma unroll
            for (int m = 0; m < 2; m++)
#pragma unroll
                for (int nt = 0; nt < 4; nt++)
                    mma16816(acc[m][nt], (const uint32_t*)&curA[m][j], &bf[nt >> 1][(nt & 1) << 1]);
        }
#pragma unroll
        for (int m = 0; m < 2; m++)
#pragma unroll
            for (int j = 0; j < 2; j++)
                curA[m][j] = nxtA[m][j];
        if (++kc == 10) kc = 0;
    }

    // activation -> z (bf16 hi/lo) [64t][136ch]
    const float* bg = g_bg + blk * 240;
    __nv_bfloat16* zh = (__nv_bfloat16*)(smb + ZHI);
    __nv_bfloat16* zl = (__nv_bfloat16*)(smb + ZLO);
#pragma unroll
    for (int m = 0; m < 2; m++) {
        int mt = 2 * wr + m;
        int ch = (mt << 3) + (lane >> 2);
        bool valid = ch < 120;
        float bf_ = valid ? bg[ch] : 0.f;
        float bg_ = valid ? bg[120 + ch] : 0.f;
#pragma unroll
        for (int nt = 0; nt < 4; nt++) {
            int tt = (wt << 5) + (nt << 3) + ((lane & 3) << 1);
#pragma unroll
            for (int q = 0; q < 2; q++) {
                float z = 0.f;
                if (valid) {
                    float f = acc[m][nt][q] + bf_;
                    float g = acc[m][nt][2 + q] + bg_;
                    z = tanhf_acc(f) * sigmoidf_(g);
                }
                __nv_bfloat16 h = __float2bfloat16(z);
                zh[(tt + q) * 136 + ch] = h;
                zl[(tt + q) * 136 + ch] = __float2bfloat16(z - __bfloat162float(h));
            }
        }
    }
    __syncthreads();

    float ac2[3][4][4];
#pragma unroll
    for (int m = 0; m < 3; m++)
#pragma unroll
        for (int n = 0; n < 4; n++)
#pragma unroll
            for (int q = 0; q < 4; q++) ac2[m][n][q] = 0.f;

    // GEMM2: A fragments from L2 per chunk, no barriers
    for (int c2 = 0; c2 < 12; c2++) {
        uint4 a2[3][2];
#pragma unroll
        for (int m = 0; m < 3; m++)
#pragma unroll
            for (int j = 0; j < 2; j++)
                a2[m][j] = A2[(((c2 * 24 + (3 * wr + m)) * 2) + j) * 32 + lane];
        const uint32_t zb = su + (((c2 >> 2) == 1) ? ZLO : ZHI);
#pragma unroll
        for (int j = 0; j < 2; j++) {
            uint32_t bf[2][4];
            const int bcol = ((c2 & 3) << 5) + j * 16 + (lane & 8);
#pragma unroll
            for (int np = 0; np < 2; np++)
                ldmB(bf[np], zb + (((wt << 5) + (np << 4) + brow) * 136 + bcol) * 2);
#pragma unroll
            for (int m = 0; m < 3; m++)
#pragma unroll
                for (int nt = 0; nt < 4; nt++)
                    mma16816(ac2[m][nt], (const uint32_t*)&a2[m][j], &bf[nt >> 1][(nt & 1) << 1]);
        }
    }

    const float* bsk = bsk_all + blk * 240;
    const float* brs = brs_all + blk * 120;
    float* skipb = g_skip + (size_t)b * 240 * L_LEN;
#pragma unroll
    for (int m = 0; m < 3; m++) {
        int mt = 3 * wr + m;
#pragma unroll
        for (int h2 = 0; h2 < 2; h2++) {
            int row = (mt << 4) + (lane >> 2) + (h2 << 3);
#pragma unroll
            for (int nt = 0; nt < 4; nt++) {
                int tt = t0 + (wt << 5) + (nt << 3) + ((lane & 3) << 1);
                float v0 = ac2[m][nt][h2 << 1], v1 = ac2[m][nt][(h2 << 1) + 1];
                if (row < 240) {
                    size_t o = (size_t)row * L_LEN + tt;
                    float bb = bsk[row];
                    if (first) { skipb[o] = v0 + bb; skipb[o + 1] = v1 + bb; }
                    else       { skipb[o] += v0 + bb; skipb[o + 1] += v1 + bb; }
                } else if (row >= 256 && row < 376) {
                    int rc = row - 256;
                    size_t o = (size_t)rc * L_LEN + tt;
                    float bb = brs[rc];
                    res_out[o]     = res_in[o]     + v0 + bb;
                    res_out[o + 1] = res_in[o + 1] + v1 + bb;
                }
            }
        }
    }
}

// ---------------- head GEMM (mma.sync, barrier-free mainloop) ----------------
#define HXHI 0
#define HXLO 33792
#define SMEM_HEAD 67584

__global__ void __launch_bounds__(512, 1) head_kernel(const float* __restrict__ bias,
                                                      float* __restrict__ outp, int which)
{
    char* smb = dynsmem;
    const uint32_t su = smem_u32(smb);
    const int tid = threadIdx.x, w = tid >> 5, lane = tid & 31;
    const int wr = w >> 1, wt = w & 1;
    const int b = blockIdx.y, t0 = blockIdx.x << 6;

    const int Kreal = which ? 256 : 240;
    const float* srcb = (which ? g_h : g_skip) + (size_t)b * Kreal * L_LEN;
    const uint4* A = (const uint4*)(which ? g_WH2f : g_WH1f);
    float* out = (which ? outp : g_h) + (size_t)b * 256 * L_LEN;

    __nv_bfloat16* xh = (__nv_bfloat16*)(smb + HXHI);
    __nv_bfloat16* xl = (__nv_bfloat16*)(smb + HXLO);
    for (int idx = tid; idx < 256 * 64; idx += 512) {
        int t = idx & 63, k = idx >> 6;
        float v = (k < Kreal) ? srcb[k * L_LEN + t0 + t] : 0.f;
        v = v > 0.f ? v : 0.f;
        __nv_bfloat16 h = __float2bfloat16(v);
        xh[t * 264 + k] = h;
        xl[t * 264 + k] = __float2bfloat16(v - __bfloat162float(h));
    }
    __syncthreads();

    float acc[2][4][4];
#pragma unroll
    for (int m = 0; m < 2; m++)
#pragma unroll
        for (int n = 0; n < 4; n++)
#pragma unroll
            for (int q = 0; q < 4; q++) acc[m][n][q] = 0.f;

    const int brow = ((lane & 16) >> 1) + (lane & 7);

    uint4 curA[2][2], nxtA[2][2];
#pragma unroll
    for (int m = 0; m < 2; m++)
#pragma unroll
        for (int j = 0; j < 2; j++)
            curA[m][j] = A[(((0 * 16 + (2 * wr + m)) * 2) + j) * 32 + lane];

    for (int c2 = 0; c2 < 24; c2++) {
        if (c2 < 23) {
#pragma unroll
            for (int m = 0; m < 2; m++)
#pragma unroll
                for (int j = 0; j < 2; j++)
                    nxtA[m][j] = A[((((c2 + 1) * 16 + (2 * wr + m)) * 2) + j) * 32 + lane];
        }
        const uint32_t xb = su + ((c2 >= 8 && c2 < 16) ? HXLO : HXHI);
#pragma unroll
        for (int j = 0; j < 2; j++) {
            uint32_t bf[2][4];
            const int bcol = ((c2 & 7) << 5) + j * 16 + (lane & 8);
#pragma unroll
            for (int np = 0; np < 2; np++)
                ldmB(bf[np], xb + (((wt << 5) + (np << 4) + brow) * 264 + bcol) * 2);
#pragma unroll
            for (int m = 0; m < 2; m++)
#pragma unroll
                for (int nt = 0; nt < 4; nt++)
                    mma16816(acc[m][nt], (const uint32_t*)&curA[m][j], &bf[nt >> 1][(nt & 1) << 1]);
        }
#pragma unroll
        for (int m = 0; m < 2; m++)
#pragma unroll
            for (int j = 0; j < 2; j++)
                curA[m][j] = nxtA[m][j];
    }

#pragma unroll
    for (int m = 0; m < 2; m++) {
        int mt = 2 * wr + m;
#pragma unroll
        for (int h2 = 0; h2 < 2; h2++) {
            int ch = (mt << 4) + (lane >> 2) + (h2 << 3);
            float bb = bias[ch];
#pragma unroll
            for (int nt = 0; nt < 4; nt++) {
                int tt = t0 + (wt << 5) + (nt << 3) + ((lane & 3) << 1);
                size_t o = (size_t)ch * L_LEN + tt;
                out[o]     = acc[m][nt][h2 << 1] + bb;
                out[o + 1] = acc[m][nt][(h2 << 1) + 1] + bb;
            }
        }
    }
}

// ---------------- launcher ----------------
extern "C" void kernel_launch(void* const* d_in, const int* in_sizes, int n_in,
                              void* d_out, int out_size)
{
    const float* wav    = (const float*)d_in[0];
    const float* mel    = (const float*)d_in[1];
    const float* w_up   = (const float*)d_in[2];
    const float* b_up   = (const float*)d_in[3];
    const float* w_in   = (const float*)d_in[4];
    const float* b_in   = (const float*)d_in[5];
    const float* w_gate = (const float*)d_in[6];
    const float* b_gate = (const float*)d_in[7];
    const float* w_cond = (const float*)d_in[8];
    const float* b_cond = (const float*)d_in[9];
    const float* w_res  = (const float*)d_in[10];
    const float* b_res  = (const float*)d_in[11];
    const float* w_skip = (const float*)d_in[12];
    const float* b_skip = (const float*)d_in[13];
    const float* w_h1   = (const float*)d_in[14];
    const float* b_h1   = (const float*)d_in[15];
    const float* w_h2   = (const float*)d_in[16];
    const float* b_h2   = (const float*)d_in[17];
    float* out = (float*)d_out;

    const int SMEM_UP = (4 * 80 * 68 + 4 * 80 * 80) * 4;
    cudaFuncSetAttribute(block_kernel,    cudaFuncAttributeMaxDynamicSharedMemorySize, SMEM_BLOCK);
    cudaFuncSetAttribute(head_kernel,     cudaFuncAttributeMaxDynamicSharedMemorySize, SMEM_HEAD);
    cudaFuncSetAttribute(upsample_kernel, cudaFuncAttributeMaxDynamicSharedMemorySize, SMEM_UP);

    prep_kernel<<<4096, 256>>>(w_gate, b_gate, w_cond, b_cond, w_res, w_skip, w_h1, w_h2);
    upsample_kernel<<<256, 256, SMEM_UP>>>(mel, w_up, b_up);
    init_kernel<<<4096, 256>>>(wav, w_in, b_in);

    dim3 grid(NT64, 4);
    for (int i = 0; i < 16; i++)
        block_kernel<<<grid, 512, SMEM_BLOCK>>>(b_skip, b_res, i, 1 << (i & 7),
                                                (i == 0) ? 1 : 0, i & 1);

    head_kernel<<<grid, 512, SMEM_HEAD>>>(b_h1, out, 0);
    head_kernel<<<grid, 512, SMEM_HEAD>>>(b_h2, out, 1);
}